// round 14
// baseline (speedup 1.0000x reference)
#include <cuda_runtime.h>
#include <cuda_bf16.h>
#include <cstdint>
#include <math.h>

#define Hh 384
#define Ww 384
#define HWsz 147456
#define NB 4

// ---------------- static device scratch ----------------
static __device__ float g_t64[(size_t)NB * 64 * HWsz];    // branch layer1 out, NHWC fp32
static __device__ float g_pool[256];
static __device__ int   g_sel[1];
static __device__ float g_xb[(size_t)NB * 32 * HWsz];     // branch out, NHWC fp32 (sel!=0)
static __device__ float g_qkv_pre[(size_t)NB * 96 * HWsz];
static __device__ float g_qkv[(size_t)NB * 96 * HWsz];
static __device__ float g_ssq[256];
static __device__ float g_S[512];
static __device__ float g_attn[512];
static __device__ float g_ff[(size_t)NB * 32 * HWsz];

// bf16 detector path (batch 0 only)
static __device__ __nv_bfloat16 g_xh[(size_t)HWsz * 32];
static __device__ __nv_bfloat16 g_det1h[(size_t)HWsz * 64];
static __device__ __nv_bfloat16 g_det2h[(size_t)HWsz * 128];
static __device__ __nv_bfloat16 g_wbf1[9 * 64 * 40];
static __device__ __nv_bfloat16 g_wbf2[2 * 2 * 9 * 64 * 40];
static __device__ __nv_bfloat16 g_wbf3[4 * 4 * 9 * 64 * 40];

// tf32 fragment-major branch weights: [0]=hvi1 [1]=hvi2 [2]=ycc1 [3]=ycc2
static __device__ uint32_t g_wt32[4][18432];

__device__ __forceinline__ float gelu_exact(float x) {
    return 0.5f * x * (1.0f + erff(x * 0.70710678118654752f));
}

// ---------------- merged weight-convert + zero kernel ----------------
__device__ __forceinline__ void cvt_one(const float* w, __nv_bfloat16* dst, int CIN, int idx) {
    int ocg = idx / (CIN * 9);
    int rem = idx - ocg * (CIN * 9);
    int cin = rem / 9, tap = rem % 9;
    int ot = ocg >> 6, oc = ocg & 63;
    int kc = cin >> 5, c = cin & 31;
    dst[((((size_t)ot * (CIN / 32) + kc) * 9 + tap) * 64 + oc) * 40 + c] = __float2bfloat16(w[idx]);
}
// tf32 fragment-major: dst[(((kc*9+tap)*MS + ms)*2 + k8)*32 + lane]*4 + reg
__device__ __forceinline__ void cvt_t32(const float* w, uint32_t* dst, int CIN, int MS, int idx) {
    int oc = idx / (CIN * 9);
    int rem = idx - oc * (CIN * 9);
    int cin = rem / 9, tap = rem % 9;
    int kc = cin >> 4, kk = cin & 15, k8 = kk >> 3, k4 = kk & 7;
    int reg  = ((oc >> 3) & 1) | ((k4 >> 2) << 1);
    int lane = (oc & 7) * 4 + (k4 & 3);
    int ms   = oc >> 4;
    uint32_t u;
    asm("cvt.rna.tf32.f32 %0, %1;" : "=r"(u) : "f"(w[idx]));
    dst[((((kc * 9 + tap) * MS + ms) * 2 + k8) * 32 + lane) * 4 + reg] = u;
}
__global__ void cvtz_k(const float* __restrict__ w1, const float* __restrict__ w2,
                       const float* __restrict__ w3,
                       const float* __restrict__ h1, const float* __restrict__ h2,
                       const float* __restrict__ y1, const float* __restrict__ y2)
{
    int idx = blockIdx.x * 256 + threadIdx.x;
    if (idx < 18432) { cvt_one(w1, g_wbf1, 32, idx); return; }
    idx -= 18432;
    if (idx < 73728) { cvt_one(w2, g_wbf2, 64, idx); return; }
    idx -= 73728;
    if (idx < 294912) { cvt_one(w3, g_wbf3, 128, idx); return; }
    idx -= 294912;
    if (idx < 512) {
        if (idx < 256) { g_pool[idx] = 0.f; g_ssq[idx] = 0.f; }
        g_S[idx] = 0.f;
        return;
    }
    idx -= 512;
    if (idx < 18432) { cvt_t32(h1, g_wt32[0], 32, 4, idx); return; }
    idx -= 18432;
    if (idx < 18432) { cvt_t32(h2, g_wt32[1], 64, 2, idx); return; }
    idx -= 18432;
    if (idx < 18432) { cvt_t32(y1, g_wt32[2], 32, 4, idx); return; }
    idx -= 18432;
    if (idx < 18432) { cvt_t32(y2, g_wt32[3], 64, 2, idx); return; }
}

// ---------------- x (fp32 NCHW b0) -> bf16 NHWC ----------------
__global__ void cvt_x_k(const float* __restrict__ x) {
    __shared__ float s[32][33];
    int p0 = blockIdx.x * 32;
    s[threadIdx.y][threadIdx.x] = x[(size_t)threadIdx.y * HWsz + p0 + threadIdx.x];
    __syncthreads();
    g_xh[(size_t)(p0 + threadIdx.y) * 32 + threadIdx.x] = __float2bfloat16(s[threadIdx.x][threadIdx.y]);
}

// ---------------- bf16 HMMA implicit-GEMM 3x3 conv, 4 rows/block (R9 tile, minBlocks=3) ----------------
template<int CIN, bool POOL>
__global__ void __launch_bounds__(256, 3) mmaconv4_k(
    const __nv_bfloat16* __restrict__ in,
    const __nv_bfloat16* __restrict__ wbf,
    const float* __restrict__ bias,
    __nv_bfloat16* __restrict__ outNHWC,
    float* __restrict__ pool,
    int Cout)
{
    const int tid  = threadIdx.x;
    const int lane = tid & 31, warp = tid >> 5;
    const int x0 = blockIdx.x * 64;
    const int y0 = blockIdx.y * 4;
    const int ot = blockIdx.z;
    const int oc0 = ot * 64;
    const int m0 = (warp & 3) << 4;
    const int nb = (warp >> 2) << 5;

    __shared__ __align__(16) unsigned char smIn[6 * 66 * 40 * 2];   // 31680
    __shared__ __align__(16) unsigned char smW[3 * 64 * 40 * 2];    // 15360 (reused as sOut)
    const uint32_t sInBs = (uint32_t)__cvta_generic_to_shared(smIn);
    const uint32_t sWBs  = (uint32_t)__cvta_generic_to_shared(smW);

    const int mrow = m0 + (lane & 7) + ((lane >> 3) & 1) * 8;
    const int kofA = ((lane >> 4) & 1) * 8;
    const int lane15 = lane & 15;
    const int rowB = lane15 & 7;
    const int kofB = (lane15 >> 3) * 8;

    float acc[4][4][4];   // [row][ntile][frag]
#pragma unroll
    for (int r = 0; r < 4; r++)
#pragma unroll
        for (int nt = 0; nt < 4; nt++)
#pragma unroll
            for (int c = 0; c < 4; c++) acc[r][nt][c] = 0.f;

    const int KC = CIN / 32;
    for (int kc = 0; kc < KC; kc++) {
        __syncthreads();
        // stage 6 input rows x 66 px x 32 ch
        for (int idx = tid; idx < 1584; idx += 256) {
            int dy = idx / 264; int rem = idx - dy * 264;
            int px = rem >> 2, cg = rem & 3;
            int gy = y0 + dy - 1, gx = x0 - 1 + px;
            uint4 v = make_uint4(0u, 0u, 0u, 0u);
            if ((unsigned)gy < 384u && (unsigned)gx < 384u)
                v = *(const uint4*)(in + ((size_t)(gy * 384 + gx)) * CIN + kc * 32 + cg * 8);
            *(uint4*)(smIn + ((dy * 66 + px) * 40 + cg * 8) * 2) = v;
        }
        const uint4* wsrc = (const uint4*)(wbf + ((size_t)(ot * KC + kc) * 9) * 64 * 40);
#pragma unroll
        for (int tg = 0; tg < 3; tg++) {       // tap row dy
            if (tg) __syncthreads();
            for (int idx = tid; idx < 960; idx += 256)
                ((uint4*)smW)[idx] = wsrc[tg * 960 + idx];
            __syncthreads();
#pragma unroll
            for (int tt = 0; tt < 3; tt++) {   // tap col dx
#pragma unroll
                for (int k16 = 0; k16 < 2; k16++) {
                    uint32_t aAddr = sWBs + (uint32_t)(((tt * 64 + mrow) * 40 + k16 * 16 + kofA) * 2);
                    uint32_t a0, a1, a2, a3;
                    asm volatile(
                        "ldmatrix.sync.aligned.m8n8.x4.shared.b16 {%0,%1,%2,%3}, [%4];"
                        : "=r"(a0), "=r"(a1), "=r"(a2), "=r"(a3) : "r"(aAddr));
#pragma unroll
                    for (int r = 0; r < 4; r++) {
                        uint32_t bBase = sInBs +
                            (uint32_t)(((((tg + r) * 66) + nb + rowB + tt) * 40 + k16 * 16 + kofB) * 2);
#pragma unroll
                        for (int nt = 0; nt < 4; nt++) {
                            uint32_t b0, b1;
                            asm volatile(
                                "ldmatrix.sync.aligned.m8n8.x2.shared.b16 {%0,%1}, [%2];"
                                : "=r"(b0), "=r"(b1) : "r"(bBase + nt * 640u));
                            asm volatile(
                                "mma.sync.aligned.m16n8k16.row.col.f32.bf16.bf16.f32 "
                                "{%0,%1,%2,%3},{%4,%5,%6,%7},{%8,%9},{%0,%1,%2,%3};\n"
                                : "+f"(acc[r][nt][0]), "+f"(acc[r][nt][1]),
                                  "+f"(acc[r][nt][2]), "+f"(acc[r][nt][3])
                                : "r"(a0), "r"(a1), "r"(a2), "r"(a3), "r"(b0), "r"(b1));
                        }
                    }
                }
            }
        }
    }
    __syncthreads();

    float blo = __ldg(&bias[oc0 + m0 + (lane >> 2)]);
    float bhi = __ldg(&bias[oc0 + m0 + (lane >> 2) + 8]);

    if (POOL) {
        float slo = 0.f, shi = 0.f;
#pragma unroll
        for (int r = 0; r < 4; r++)
#pragma unroll
            for (int nt = 0; nt < 4; nt++) {
                slo += fmaxf(acc[r][nt][0] + blo, 0.f) + fmaxf(acc[r][nt][1] + blo, 0.f);
                shi += fmaxf(acc[r][nt][2] + bhi, 0.f) + fmaxf(acc[r][nt][3] + bhi, 0.f);
            }
        slo += __shfl_xor_sync(0xffffffffu, slo, 1);
        slo += __shfl_xor_sync(0xffffffffu, slo, 2);
        shi += __shfl_xor_sync(0xffffffffu, shi, 1);
        shi += __shfl_xor_sync(0xffffffffu, shi, 2);
        if ((lane & 3) == 0) {
            atomicAdd(&pool[oc0 + m0 + (lane >> 2)], slo);
            atomicAdd(&pool[oc0 + m0 + (lane >> 2) + 8], shi);
        }
    } else {
        __nv_bfloat16* sOut = (__nv_bfloat16*)smW;   // weights no longer needed
#pragma unroll
        for (int r = 0; r < 4; r++) {
            if (r) __syncthreads();
#pragma unroll
            for (int nt = 0; nt < 4; nt++) {
                int px = nb + nt * 8 + (lane & 3) * 2;
                int oc = m0 + (lane >> 2);
                sOut[px * 64 + oc]           = __float2bfloat16(fmaxf(acc[r][nt][0] + blo, 0.f));
                sOut[(px + 1) * 64 + oc]     = __float2bfloat16(fmaxf(acc[r][nt][1] + blo, 0.f));
                sOut[px * 64 + oc + 8]       = __float2bfloat16(fmaxf(acc[r][nt][2] + bhi, 0.f));
                sOut[(px + 1) * 64 + oc + 8] = __float2bfloat16(fmaxf(acc[r][nt][3] + bhi, 0.f));
            }
            __syncthreads();
            for (int idx = tid; idx < 512; idx += 256) {
                int px = idx >> 3, og = idx & 7;
                *(uint4*)(outNHWC + ((size_t)((y0 + r) * 384 + x0 + px)) * Cout + oc0 + og * 8) =
                    *(const uint4*)(sOut + px * 64 + og * 8);
            }
        }
    }
}

// ---------------- TF32 MMA implicit-GEMM 3x3 conv (branch path, pad=1) ----------------
template<int CIN, int COUT, bool INNHWC>
__global__ void __launch_bounds__(256) tf32conv_k(
    const float* __restrict__ in,
    const uint32_t* __restrict__ wfrag,
    const float* __restrict__ bias,
    float* __restrict__ outNHWC,
    const int* __restrict__ selp, int selv)
{
    if (__ldg(selp) != selv) return;
    constexpr int MS = COUT / 16;
    constexpr int NS = 8 / MS;
    constexpr int NT = 8 / NS;
    constexpr int WCNT = 3 * MS * 2 * 32 * 4;

    const int tid  = threadIdx.x;
    const int lane = tid & 31, warp = tid >> 5;
    const int x0 = blockIdx.x * 64;
    const int y0 = blockIdx.y * 4;
    const int b  = blockIdx.z;
    const int m0 = (warp % MS) * 16;
    const int nb = (warp / MS) * (64 / NS);

    const float* inb = in + (size_t)b * CIN * HWsz;
    float* outb = outNHWC + (size_t)b * HWsz * COUT;

    __shared__ uint32_t sIn[6 * 66 * 20];
    __shared__ __align__(16) uint32_t sW[3 * 4 * 2 * 32 * 4];

    float acc[4][NT][4];
#pragma unroll
    for (int r = 0; r < 4; r++)
#pragma unroll
        for (int nt = 0; nt < NT; nt++)
#pragma unroll
            for (int c = 0; c < 4; c++) acc[r][nt][c] = 0.f;

    const int KC = CIN / 16;
    for (int kc = 0; kc < KC; kc++) {
        __syncthreads();
        for (int idx = tid; idx < 6336; idx += 256) {
            int cc, dy, px;
            if (INNHWC) { cc = idx & 15; int t = idx >> 4; px = t % 66; dy = t / 66; }
            else        { cc = idx / 396; int rem = idx - cc * 396; dy = rem / 66; px = rem - dy * 66; }
            int gy = y0 + dy - 1, gx = x0 - 1 + px;
            float v = 0.f;
            if ((unsigned)gy < 384u && (unsigned)gx < 384u)
                v = INNHWC ? inb[(size_t)(gy * 384 + gx) * CIN + kc * 16 + cc]
                           : inb[(size_t)(kc * 16 + cc) * HWsz + gy * 384 + gx];
            uint32_t u;
            asm("cvt.rna.tf32.f32 %0, %1;" : "=r"(u) : "f"(v));
            sIn[(dy * 66 + px) * 20 + cc] = u;
        }
        const uint4* wsrc = (const uint4*)(wfrag + (size_t)kc * 9 * MS * 2 * 32 * 4);
#pragma unroll
        for (int tg = 0; tg < 3; tg++) {
            if (tg) __syncthreads();
            for (int idx = tid; idx < WCNT / 4; idx += 256)
                ((uint4*)sW)[idx] = wsrc[tg * (WCNT / 4) + idx];
            __syncthreads();
#pragma unroll
            for (int tt = 0; tt < 3; tt++) {
#pragma unroll
                for (int k8 = 0; k8 < 2; k8++) {
                    uint4 af = *(const uint4*)&sW[(((tt * MS + (m0 >> 4)) * 2 + k8) * 32 + lane) * 4];
#pragma unroll
                    for (int r = 0; r < 4; r++) {
                        int wbase = ((tg + r) * 66 + nb + (lane >> 2) + tt) * 20 + k8 * 8 + (lane & 3);
#pragma unroll
                        for (int nt = 0; nt < NT; nt++) {
                            uint32_t b0 = sIn[wbase + nt * 160];
                            uint32_t b1 = sIn[wbase + nt * 160 + 4];
                            asm volatile(
                                "mma.sync.aligned.m16n8k8.row.col.f32.tf32.tf32.f32 "
                                "{%0,%1,%2,%3},{%4,%5,%6,%7},{%8,%9},{%0,%1,%2,%3};\n"
                                : "+f"(acc[r][nt][0]), "+f"(acc[r][nt][1]),
                                  "+f"(acc[r][nt][2]), "+f"(acc[r][nt][3])
                                : "r"(af.x), "r"(af.y), "r"(af.z), "r"(af.w),
                                  "r"(b0), "r"(b1));
                        }
                    }
                }
            }
        }
    }
    __syncthreads();

    float blo = __ldg(&bias[m0 + (lane >> 2)]);
    float bhi = __ldg(&bias[m0 + (lane >> 2) + 8]);

    float* sOut = (float*)sIn;
#pragma unroll
    for (int r = 0; r < 4; r++) {
        if (r) __syncthreads();
#pragma unroll
        for (int nt = 0; nt < NT; nt++) {
            int px = nb + nt * 8 + (lane & 3) * 2;
            int oc = m0 + (lane >> 2);
            sOut[px * COUT + oc]           = fmaxf(acc[r][nt][0] + blo, 0.f);
            sOut[(px + 1) * COUT + oc]     = fmaxf(acc[r][nt][1] + blo, 0.f);
            sOut[px * COUT + oc + 8]       = fmaxf(acc[r][nt][2] + bhi, 0.f);
            sOut[(px + 1) * COUT + oc + 8] = fmaxf(acc[r][nt][3] + bhi, 0.f);
        }
        __syncthreads();
        for (int idx = tid; idx < 16 * COUT; idx += 256) {
            int px = idx / (COUT / 4), og = idx % (COUT / 4);
            *(float4*)(outb + (size_t)((y0 + r) * 384 + x0 + px) * COUT + og * 4) =
                *(const float4*)(sOut + px * COUT + og * 4);
        }
    }
}

// ---------------- logits + argmax ----------------
__global__ void logits_k(const float* __restrict__ fcw, const float* __restrict__ fcb) {
    __shared__ float l[3];
    int t = threadIdx.x;
    if (t < 3) {
        float s = 0.f;
        const float inv = 1.0f / (float)HWsz;
        for (int k = 0; k < 256; k++)
            s = fmaf(fcw[t * 256 + k], g_pool[k] * inv, s);
        l[t] = s + fcb[t];
    }
    __syncthreads();
    if (t == 0) {
        int best = 0; float bv = l[0];
        if (l[1] > bv) { bv = l[1]; best = 1; }
        if (l[2] > bv) { bv = l[2]; best = 2; }
        g_sel[0] = best;
    }
}

// ---------------- fused LayerNorm + 1x1 pwconv (32 -> 96), dual src layout ----------------
__global__ void __launch_bounds__(128) ln_pw_k(
    const float* __restrict__ x,
    const float* __restrict__ lnw, const float* __restrict__ lnb,
    const float* __restrict__ pww)
{
    __shared__ float s_w[96 * 32];
    __shared__ float s_lw[32], s_lb[32];
    int tid = threadIdx.x;
    for (int i = tid; i < 96 * 32; i += 128) s_w[i] = pww[i];
    if (tid < 32) { s_lw[tid] = lnw[tid]; s_lb[tid] = lnb[tid]; }
    __syncthreads();
    const int sel = __ldg(g_sel);

    size_t pair = (size_t)blockIdx.x * 128 + tid;
    size_t gp = pair * 2;
    int b = (int)(gp / HWsz);
    int p = (int)(gp % HWsz);

    float a0[32], a1[32];
    if (sel == 0) {
#pragma unroll
        for (int c = 0; c < 32; c++) {
            float2 v = *(const float2*)&x[(size_t)(b * 32 + c) * HWsz + p];
            a0[c] = v.x; a1[c] = v.y;
        }
    } else {
        const float4* r0 = (const float4*)&g_xb[((size_t)b * HWsz + p) * 32];
        const float4* r1 = (const float4*)&g_xb[((size_t)b * HWsz + p + 1) * 32];
#pragma unroll
        for (int q = 0; q < 8; q++) {
            float4 v0 = r0[q], v1 = r1[q];
            a0[q * 4] = v0.x; a0[q * 4 + 1] = v0.y; a0[q * 4 + 2] = v0.z; a0[q * 4 + 3] = v0.w;
            a1[q * 4] = v1.x; a1[q * 4 + 1] = v1.y; a1[q * 4 + 2] = v1.z; a1[q * 4 + 3] = v1.w;
        }
    }
    float m0 = 0.f, m1 = 0.f;
#pragma unroll
    for (int c = 0; c < 32; c++) { m0 += a0[c]; m1 += a1[c]; }
    m0 *= (1.f / 32.f); m1 *= (1.f / 32.f);
    float v0 = 0.f, v1 = 0.f;
#pragma unroll
    for (int c = 0; c < 32; c++) {
        float d0 = a0[c] - m0, d1 = a1[c] - m1;
        v0 = fmaf(d0, d0, v0); v1 = fmaf(d1, d1, v1);
    }
    float r0 = rsqrtf(v0 * (1.f / 32.f) + 1e-6f);
    float r1 = rsqrtf(v1 * (1.f / 32.f) + 1e-6f);
#pragma unroll
    for (int c = 0; c < 32; c++) {
        a0[c] = fmaf((a0[c] - m0) * r0, s_lw[c], s_lb[c]);
        a1[c] = fmaf((a1[c] - m1) * r1, s_lw[c], s_lb[c]);
    }
    for (int oc = 0; oc < 96; oc++) {
        float acc0 = 0.f, acc1 = 0.f;
#pragma unroll
        for (int c = 0; c < 32; c++) {
            float w = s_w[oc * 32 + c];
            acc0 = fmaf(w, a0[c], acc0);
            acc1 = fmaf(w, a1[c], acc1);
        }
        float2 o; o.x = acc0; o.y = acc1;
        *(float2*)&g_qkv_pre[(size_t)(b * 96 + oc) * HWsz + p] = o;
    }
}

// ---------------- depthwise 3x3, 4 px/thread, optional gelu ----------------
__global__ void dw4_k(const float* __restrict__ in, const float* __restrict__ w,
                      float* __restrict__ out, int Cn, int doGelu, int totalQuads)
{
    int idx = blockIdx.x * 256 + threadIdx.x;
    if (idx >= totalQuads) return;
    int plane = idx / 36864;
    int q = idx - plane * 36864;
    int y = q / 96, qx = q - y * 96;
    int x0 = qx * 4;
    int c = plane % Cn;
    const float* ip = in + (size_t)plane * HWsz;
    const float* wp = w + c * 9;
    float wr[9];
#pragma unroll
    for (int t = 0; t < 9; t++) wr[t] = __ldg(&wp[t]);
    float o[4] = {0.f, 0.f, 0.f, 0.f};
    if (y >= 1 && y <= 382 && qx >= 1 && qx <= 94) {
#pragma unroll
        for (int dy = 0; dy < 3; dy++) {
            const float* row = ip + (size_t)(y + dy - 1) * Ww + x0;
            float l = row[-1];
            float4 m = *(const float4*)row;
            float rr = row[4];
            float w0 = wr[dy * 3], w1 = wr[dy * 3 + 1], w2 = wr[dy * 3 + 2];
            o[0] = fmaf(w0, l,   fmaf(w1, m.x, fmaf(w2, m.y, o[0])));
            o[1] = fmaf(w0, m.x, fmaf(w1, m.y, fmaf(w2, m.z, o[1])));
            o[2] = fmaf(w0, m.y, fmaf(w1, m.z, fmaf(w2, m.w, o[2])));
            o[3] = fmaf(w0, m.z, fmaf(w1, m.w, fmaf(w2, rr,  o[3])));
        }
    } else {
#pragma unroll
        for (int j = 0; j < 4; j++) {
            int x = x0 + j;
            float s = 0.f;
#pragma unroll
            for (int dy = 0; dy < 3; dy++) {
                int yy = y + dy - 1;
                if (yy < 0 || yy >= Hh) continue;
#pragma unroll
                for (int dx = 0; dx < 3; dx++) {
                    int xx = x + dx - 1;
                    if (xx < 0 || xx >= Ww) continue;
                    s = fmaf(wr[dy * 3 + dx], ip[(size_t)yy * Ww + xx], s);
                }
            }
            o[j] = s;
        }
    }
    if (doGelu) {
#pragma unroll
        for (int j = 0; j < 4; j++) o[j] = gelu_exact(o[j]);
    }
    *(float4*)(out + (size_t)plane * HWsz + (size_t)y * Ww + x0) = make_float4(o[0], o[1], o[2], o[3]);
}

// ---------------- fused sumsq + gram, atomic accumulate ----------------
__global__ void __launch_bounds__(256) sg_k() {
    int bid = blockIdx.x;
    int chunk = bid & 15, h = (bid >> 4) & 7, b = bid >> 7;
    const float* qp = g_qkv + (size_t)(b * 96 + h * 4) * HWsz;
    const float* kp = g_qkv + (size_t)(b * 96 + 32 + h * 4) * HWsz;
    float acc[24];
#pragma unroll
    for (int v = 0; v < 24; v++) acc[v] = 0.f;
    int i0 = chunk * 9216;
    for (int i = i0 + threadIdx.x; i < i0 + 9216; i += 256) {
        float qv[4], kv[4];
#pragma unroll
        for (int c = 0; c < 4; c++) {
            qv[c] = qp[(size_t)c * HWsz + i];
            kv[c] = kp[(size_t)c * HWsz + i];
        }
#pragma unroll
        for (int c = 0; c < 4; c++) {
            acc[16 + c] = fmaf(qv[c], qv[c], acc[16 + c]);
            acc[20 + c] = fmaf(kv[c], kv[c], acc[20 + c]);
#pragma unroll
            for (int d = 0; d < 4; d++)
                acc[c * 4 + d] = fmaf(qv[c], kv[d], acc[c * 4 + d]);
        }
    }
#pragma unroll
    for (int v = 0; v < 24; v++)
#pragma unroll
        for (int off = 16; off; off >>= 1)
            acc[v] += __shfl_down_sync(0xffffffffu, acc[v], off);
    __shared__ float sh[8][24];
    int warp = threadIdx.x >> 5, lane = threadIdx.x & 31;
    if (lane == 0)
#pragma unroll
        for (int v = 0; v < 24; v++) sh[warp][v] = acc[v];
    __syncthreads();
    if (threadIdx.x < 24) {
        float s = 0.f;
#pragma unroll
        for (int wq = 0; wq < 8; wq++) s += sh[wq][threadIdx.x];
        int v = threadIdx.x;
        if (v < 16)      atomicAdd(&g_S[(b * 8 + h) * 16 + v], s);
        else if (v < 20) atomicAdd(&g_ssq[b * 32 + h * 4 + (v - 16)], s);
        else             atomicAdd(&g_ssq[128 + b * 32 + h * 4 + (v - 20)], s);
    }
}

// ---------------- normalize + temperature + softmax ----------------
__global__ void attn_k(const float* __restrict__ temp) {
    int t = threadIdx.x;
    if (t >= 32) return;
    int b = t >> 3, h = t & 7;
    float nq[4], nk[4];
#pragma unroll
    for (int c = 0; c < 4; c++) {
        nq[c] = fmaxf(sqrtf(g_ssq[b * 32 + h * 4 + c]), 1e-12f);
        nk[c] = fmaxf(sqrtf(g_ssq[128 + b * 32 + h * 4 + c]), 1e-12f);
    }
    float tp = temp[h];
    float A[16];
#pragma unroll
    for (int c = 0; c < 4; c++)
#pragma unroll
        for (int d = 0; d < 4; d++)
            A[c * 4 + d] = g_S[(b * 8 + h) * 16 + c * 4 + d] / (nq[c] * nk[d]) * tp;
#pragma unroll
    for (int c = 0; c < 4; c++) {
        float m = A[c * 4];
#pragma unroll
        for (int d = 1; d < 4; d++) m = fmaxf(m, A[c * 4 + d]);
        float sum = 0.f;
#pragma unroll
        for (int d = 0; d < 4; d++) { A[c * 4 + d] = expf(A[c * 4 + d] - m); sum += A[c * 4 + d]; }
        float inv = 1.f / sum;
#pragma unroll
        for (int d = 0; d < 4; d++) g_attn[(b * 8 + h) * 16 + c * 4 + d] = A[c * 4 + d] * inv;
    }
}

// ---------------- fused: attn@v -> proj -> +res -> ff1 -> gelu, dual res layout ----------------
__global__ void __launch_bounds__(128) outproj_k(
    const float* __restrict__ x,
    const float* __restrict__ projw, const float* __restrict__ ff1w)
{
    __shared__ float s_at[128], s_pw[1024], s_fw[1024];
    int b = blockIdx.z;
    int tid = threadIdx.x;
    for (int i = tid; i < 1024; i += 128) { s_pw[i] = projw[i]; s_fw[i] = ff1w[i]; }
    if (tid < 128) s_at[tid] = g_attn[b * 128 + tid];
    __syncthreads();
    const int sel = __ldg(g_sel);

    int p = blockIdx.x * 128 + tid;
    float v[32];
#pragma unroll
    for (int c = 0; c < 32; c++)
        v[c] = g_qkv[(size_t)(b * 96 + 64 + c) * HWsz + p];
    float o[32];
#pragma unroll
    for (int c = 0; c < 32; c++) {
        int h = c >> 2, ci = c & 3;
        const float* at = &s_at[h * 16 + ci * 4];
        int vb = c & ~3;
        o[c] = at[0] * v[vb] + at[1] * v[vb + 1] + at[2] * v[vb + 2] + at[3] * v[vb + 3];
    }
    float resv[32];
    if (sel == 0) {
#pragma unroll
        for (int c = 0; c < 32; c++)
            resv[c] = x[(size_t)(b * 32 + c) * HWsz + p];
    } else {
        const float4* rp = (const float4*)&g_xb[((size_t)b * HWsz + p) * 32];
#pragma unroll
        for (int q = 0; q < 8; q++) {
            float4 vv = rp[q];
            resv[q * 4] = vv.x; resv[q * 4 + 1] = vv.y; resv[q * 4 + 2] = vv.z; resv[q * 4 + 3] = vv.w;
        }
    }
    float y[32];
#pragma unroll
    for (int c = 0; c < 32; c++) {
        float acc = resv[c];
#pragma unroll
        for (int c2 = 0; c2 < 32; c2++)
            acc = fmaf(s_pw[c * 32 + c2], o[c2], acc);
        y[c] = acc;
    }
#pragma unroll
    for (int c = 0; c < 32; c++) {
        float acc = 0.f;
#pragma unroll
        for (int c2 = 0; c2 < 32; c2++)
            acc = fmaf(s_fw[c * 32 + c2], y[c2], acc);
        g_ff[(size_t)(b * 32 + c) * HWsz + p] = gelu_exact(acc);
    }
}

// ---------------- launch ----------------
extern "C" void kernel_launch(void* const* d_in, const int* in_sizes, int n_in,
                              void* d_out, int out_size)
{
    const float* x       = (const float*)d_in[0];
    const float* ln_w    = (const float*)d_in[1];
    const float* ln_b    = (const float*)d_in[2];
    const float* temper  = (const float*)d_in[3];
    const float* pw_w    = (const float*)d_in[4];
    const float* dw_w    = (const float*)d_in[5];
    const float* proj_w  = (const float*)d_in[6];
    const float* ff1_w   = (const float*)d_in[7];
    const float* ffdw_w  = (const float*)d_in[8];
    const float* det_w1  = (const float*)d_in[9];
    const float* det_b1  = (const float*)d_in[10];
    const float* det_w2  = (const float*)d_in[11];
    const float* det_b2  = (const float*)d_in[12];
    const float* det_w3  = (const float*)d_in[13];
    const float* det_b3  = (const float*)d_in[14];
    const float* det_fcw = (const float*)d_in[15];
    const float* det_fcb = (const float*)d_in[16];
    const float* hvi_w1  = (const float*)d_in[17];
    const float* hvi_b1  = (const float*)d_in[18];
    const float* hvi_w2  = (const float*)d_in[19];
    const float* hvi_b2  = (const float*)d_in[20];
    const float* ycc_w1  = (const float*)d_in[21];
    const float* ycc_b1  = (const float*)d_in[22];
    const float* ycc_w2  = (const float*)d_in[23];
    const float* ycc_b2  = (const float*)d_in[24];
    float* outp = (float*)d_out;

    float *p_t64, *p_pool, *p_xb, *p_qkv_pre, *p_qkv, *p_ff;
    int* p_sel;
    __nv_bfloat16 *p_xh, *p_det1h, *p_det2h, *p_wbf1, *p_wbf2, *p_wbf3;
    uint32_t* p_wt32;
    cudaGetSymbolAddress((void**)&p_t64, g_t64);
    cudaGetSymbolAddress((void**)&p_pool, g_pool);
    cudaGetSymbolAddress((void**)&p_sel,  g_sel);
    cudaGetSymbolAddress((void**)&p_xb,   g_xb);
    cudaGetSymbolAddress((void**)&p_qkv_pre, g_qkv_pre);
    cudaGetSymbolAddress((void**)&p_qkv,  g_qkv);
    cudaGetSymbolAddress((void**)&p_ff,   g_ff);
    cudaGetSymbolAddress((void**)&p_xh,   g_xh);
    cudaGetSymbolAddress((void**)&p_det1h, g_det1h);
    cudaGetSymbolAddress((void**)&p_det2h, g_det2h);
    cudaGetSymbolAddress((void**)&p_wbf1, g_wbf1);
    cudaGetSymbolAddress((void**)&p_wbf2, g_wbf2);
    cudaGetSymbolAddress((void**)&p_wbf3, g_wbf3);
    cudaGetSymbolAddress((void**)&p_wt32, g_wt32);

    // setup
    cvtz_k<<<(18432 + 73728 + 294912 + 512 + 4 * 18432 + 255) / 256, 256>>>(
        det_w1, det_w2, det_w3, hvi_w1, hvi_w2, ycc_w1, ycc_w2);
    cvt_x_k<<<HWsz / 32, dim3(32, 32)>>>(x);

    // detector (batch 0, bf16 HMMA); 4th launch = mmaconv4<64> (ncu target)
    mmaconv4_k<32,  false><<<dim3(6, 96, 1), 256>>>(p_xh,    p_wbf1, det_b1, p_det1h, nullptr, 64);
    mmaconv4_k<64,  false><<<dim3(6, 96, 2), 256>>>(p_det1h, p_wbf2, det_b2, p_det2h, nullptr, 128);
    mmaconv4_k<128, true ><<<dim3(6, 96, 4), 256>>>(p_det2h, p_wbf3, det_b3, nullptr, p_pool, 256);
    logits_k<<<1, 32>>>(det_fcw, det_fcb);

    // branch (TF32 MMA, NHWC output; predicated on g_sel)
    tf32conv_k<32, 64, false><<<dim3(6, 96, 4), 256>>>(x,     p_wt32 + 0 * 18432, hvi_b1, p_t64, p_sel, 1);
    tf32conv_k<64, 32, true ><<<dim3(6, 96, 4), 256>>>(p_t64, p_wt32 + 1 * 18432, hvi_b2, p_xb,  p_sel, 1);
    tf32conv_k<32, 64, false><<<dim3(6, 96, 4), 256>>>(x,     p_wt32 + 2 * 18432, ycc_b1, p_t64, p_sel, 2);
    tf32conv_k<64, 32, true ><<<dim3(6, 96, 4), 256>>>(p_t64, p_wt32 + 3 * 18432, ycc_b2, p_xb,  p_sel, 2);

    // LN + pw 1x1
    ln_pw_k<<<(NB * HWsz / 2) / 128, 128>>>(x, ln_w, ln_b, pw_w);
    // depthwise 3x3 (96 ch)
    dw4_k<<<(NB * 96 * 36864 + 255) / 256, 256>>>(p_qkv_pre, dw_w, p_qkv, 96, 0, NB * 96 * 36864);
    // fused sumsq + gram
    sg_k<<<512, 256>>>();
    attn_k<<<1, 32>>>(temper);
    // attn apply + proj + residual + ff1 + gelu
    outproj_k<<<dim3(HWsz / 128, 1, NB), 128>>>(x, proj_w, ff1_w);
    // ffdw depthwise + gelu -> out
    dw4_k<<<(NB * 32 * 36864 + 255) / 256, 256>>>(p_ff, ffdw_w, outp, 32, 1, NB * 32 * 36864);

    (void)in_sizes; (void)n_in; (void)out_size;
}

// round 15
// speedup vs baseline: 1.0962x; 1.0962x over previous
#include <cuda_runtime.h>
#include <cuda_bf16.h>
#include <cstdint>
#include <math.h>

#define Hh 384
#define Ww 384
#define HWsz 147456
#define NB 4

// ---------------- static device scratch ----------------
static __device__ float g_t64[(size_t)NB * 64 * HWsz];    // branch layer1 out, NHWC fp32
static __device__ float g_pool[256];
static __device__ int   g_sel[1];
static __device__ float g_xb[(size_t)NB * 32 * HWsz];     // branch out, NHWC fp32 (sel!=0)
static __device__ float g_qkv_pre[(size_t)NB * 96 * HWsz];
static __device__ float g_qkv[(size_t)NB * 96 * HWsz];
static __device__ float g_ssq[256];
static __device__ float g_S[512];
static __device__ float g_attn[512];
static __device__ float g_ff[(size_t)NB * 32 * HWsz];

// bf16 detector path (batch 0 only)
static __device__ __nv_bfloat16 g_xh[(size_t)HWsz * 32];
static __device__ __nv_bfloat16 g_det1h[(size_t)HWsz * 64];
static __device__ __nv_bfloat16 g_det2h[(size_t)HWsz * 128];
static __device__ __nv_bfloat16 g_wbf1[9 * 64 * 40];
static __device__ __nv_bfloat16 g_wbf2[2 * 2 * 9 * 64 * 40];
static __device__ __nv_bfloat16 g_wbf3[4 * 4 * 9 * 64 * 40];

// tf32 fragment-major branch weights: [0]=hvi1 [1]=hvi2 [2]=ycc1 [3]=ycc2
static __device__ uint32_t g_wt32[4][18432];

__device__ __forceinline__ float gelu_exact(float x) {
    return 0.5f * x * (1.0f + erff(x * 0.70710678118654752f));
}

// ---------------- merged weight-convert + zero kernel ----------------
__device__ __forceinline__ void cvt_one(const float* w, __nv_bfloat16* dst, int CIN, int idx) {
    int ocg = idx / (CIN * 9);
    int rem = idx - ocg * (CIN * 9);
    int cin = rem / 9, tap = rem % 9;
    int ot = ocg >> 6, oc = ocg & 63;
    int kc = cin >> 5, c = cin & 31;
    dst[((((size_t)ot * (CIN / 32) + kc) * 9 + tap) * 64 + oc) * 40 + c] = __float2bfloat16(w[idx]);
}
// tf32 fragment-major: dst[(((kc*9+tap)*MS + ms)*2 + k8)*32 + lane]*4 + reg
__device__ __forceinline__ void cvt_t32(const float* w, uint32_t* dst, int CIN, int MS, int idx) {
    int oc = idx / (CIN * 9);
    int rem = idx - oc * (CIN * 9);
    int cin = rem / 9, tap = rem % 9;
    int kc = cin >> 4, kk = cin & 15, k8 = kk >> 3, k4 = kk & 7;
    int reg  = ((oc >> 3) & 1) | ((k4 >> 2) << 1);
    int lane = (oc & 7) * 4 + (k4 & 3);
    int ms   = oc >> 4;
    uint32_t u;
    asm("cvt.rna.tf32.f32 %0, %1;" : "=r"(u) : "f"(w[idx]));
    dst[((((kc * 9 + tap) * MS + ms) * 2 + k8) * 32 + lane) * 4 + reg] = u;
}
__global__ void cvtz_k(const float* __restrict__ w1, const float* __restrict__ w2,
                       const float* __restrict__ w3,
                       const float* __restrict__ h1, const float* __restrict__ h2,
                       const float* __restrict__ y1, const float* __restrict__ y2)
{
    int idx = blockIdx.x * 256 + threadIdx.x;
    if (idx < 18432) { cvt_one(w1, g_wbf1, 32, idx); return; }
    idx -= 18432;
    if (idx < 73728) { cvt_one(w2, g_wbf2, 64, idx); return; }
    idx -= 73728;
    if (idx < 294912) { cvt_one(w3, g_wbf3, 128, idx); return; }
    idx -= 294912;
    if (idx < 512) {
        if (idx < 256) { g_pool[idx] = 0.f; g_ssq[idx] = 0.f; }
        g_S[idx] = 0.f;
        return;
    }
    idx -= 512;
    if (idx < 18432) { cvt_t32(h1, g_wt32[0], 32, 4, idx); return; }
    idx -= 18432;
    if (idx < 18432) { cvt_t32(h2, g_wt32[1], 64, 2, idx); return; }
    idx -= 18432;
    if (idx < 18432) { cvt_t32(y1, g_wt32[2], 32, 4, idx); return; }
    idx -= 18432;
    if (idx < 18432) { cvt_t32(y2, g_wt32[3], 64, 2, idx); return; }
}

// ---------------- x (fp32 NCHW b0) -> bf16 NHWC ----------------
__global__ void cvt_x_k(const float* __restrict__ x) {
    __shared__ float s[32][33];
    int p0 = blockIdx.x * 32;
    s[threadIdx.y][threadIdx.x] = x[(size_t)threadIdx.y * HWsz + p0 + threadIdx.x];
    __syncthreads();
    g_xh[(size_t)(p0 + threadIdx.y) * 32 + threadIdx.x] = __float2bfloat16(s[threadIdx.x][threadIdx.y]);
}

// ---------------- bf16 HMMA implicit-GEMM 3x3 conv, all-taps-resident (dynamic smem) ----------------
// Tile: 64 oc x 64 px x 4 rows. 8 warps = 4 m-slices(16oc) x 2 n-halves(32px).
// ALL 9 tap-rows of weights resident in smem -> each B fragment (input row s) is loaded
// ONCE and feeds up to 3 MMAs (tap rows tg with r = s - tg in [0,4)).
// Wavefronts per warp per kc: B 288 + A 72 for 288 MMAs (1.25 wf/MMA vs 2.25 in R9 cfg).
// Dynamic smem: 31680 (input) + 46080 (weights) = 77760 B; 2 CTAs/SM.
template<int CIN, bool POOL>
__global__ void __launch_bounds__(256) mmaconvW_k(
    const __nv_bfloat16* __restrict__ in,
    const __nv_bfloat16* __restrict__ wbf,
    const float* __restrict__ bias,
    __nv_bfloat16* __restrict__ outNHWC,
    float* __restrict__ pool,
    int Cout)
{
    extern __shared__ __align__(16) unsigned char smraw[];
    unsigned char* smIn = smraw;                // bf16 [(dy*66+px)*40 + c], 31680 B
    unsigned char* smW  = smraw + 31680;        // bf16 [tap(9)][oc(64)][40],  46080 B

    const int tid  = threadIdx.x;
    const int lane = tid & 31, warp = tid >> 5;
    const int x0 = blockIdx.x * 64;
    const int y0 = blockIdx.y * 4;
    const int ot = blockIdx.z;
    const int oc0 = ot * 64;
    const int m0 = (warp & 3) << 4;
    const int nb = (warp >> 2) << 5;

    const uint32_t sInBs = (uint32_t)__cvta_generic_to_shared(smIn);
    const uint32_t sWBs  = (uint32_t)__cvta_generic_to_shared(smW);

    const int mrow = m0 + (lane & 7) + ((lane >> 3) & 1) * 8;
    const int kofA = ((lane >> 4) & 1) * 8;
    const int lane15 = lane & 15;
    const int rowB = lane15 & 7;
    const int kofB = (lane15 >> 3) * 8;

    float acc[4][4][4];   // [row][ntile][frag]
#pragma unroll
    for (int r = 0; r < 4; r++)
#pragma unroll
        for (int nt = 0; nt < 4; nt++)
#pragma unroll
            for (int c = 0; c < 4; c++) acc[r][nt][c] = 0.f;

    const int KC = CIN / 32;
    for (int kc = 0; kc < KC; kc++) {
        __syncthreads();
        // stage 6 input rows x 66 px x 32 ch
        for (int idx = tid; idx < 1584; idx += 256) {
            int dy = idx / 264; int rem = idx - dy * 264;
            int px = rem >> 2, cg = rem & 3;
            int gy = y0 + dy - 1, gx = x0 - 1 + px;
            uint4 v = make_uint4(0u, 0u, 0u, 0u);
            if ((unsigned)gy < 384u && (unsigned)gx < 384u)
                v = *(const uint4*)(in + ((size_t)(gy * 384 + gx)) * CIN + kc * 32 + cg * 8);
            *(uint4*)(smIn + ((dy * 66 + px) * 40 + cg * 8) * 2) = v;
        }
        // stage ALL 9 taps of weights for this (ot, kc)
        const uint4* wsrc = (const uint4*)(wbf + ((size_t)(ot * KC + kc) * 9) * 64 * 40);
        for (int idx = tid; idx < 2880; idx += 256)
            ((uint4*)smW)[idx] = wsrc[idx];
        __syncthreads();

#pragma unroll
        for (int tt = 0; tt < 3; tt++) {       // tap col dx
#pragma unroll
            for (int k16 = 0; k16 < 2; k16++) {
                // A fragments for all 3 tap rows (tap = tg*3 + tt)
                uint32_t a[3][4];
#pragma unroll
                for (int tg = 0; tg < 3; tg++) {
                    uint32_t aAddr = sWBs + (uint32_t)(
                        (((tg * 3 + tt) * 64 + mrow) * 40 + k16 * 16 + kofA) * 2);
                    asm volatile(
                        "ldmatrix.sync.aligned.m8n8.x4.shared.b16 {%0,%1,%2,%3}, [%4];"
                        : "=r"(a[tg][0]), "=r"(a[tg][1]), "=r"(a[tg][2]), "=r"(a[tg][3])
                        : "r"(aAddr));
                }
#pragma unroll
                for (int s = 0; s < 6; s++) {  // absolute input row
                    uint32_t bBase = sInBs +
                        (uint32_t)(((s * 66 + nb + rowB + tt) * 40 + k16 * 16 + kofB) * 2);
#pragma unroll
                    for (int nt = 0; nt < 4; nt++) {
                        uint32_t b0, b1;
                        asm volatile(
                            "ldmatrix.sync.aligned.m8n8.x2.shared.b16 {%0,%1}, [%2];"
                            : "=r"(b0), "=r"(b1) : "r"(bBase + nt * 640u));
#pragma unroll
                        for (int tg = 0; tg < 3; tg++) {
                            int r = s - tg;
                            if (r >= 0 && r < 4) {
                                asm volatile(
                                    "mma.sync.aligned.m16n8k16.row.col.f32.bf16.bf16.f32 "
                                    "{%0,%1,%2,%3},{%4,%5,%6,%7},{%8,%9},{%0,%1,%2,%3};\n"
                                    : "+f"(acc[r][nt][0]), "+f"(acc[r][nt][1]),
                                      "+f"(acc[r][nt][2]), "+f"(acc[r][nt][3])
                                    : "r"(a[tg][0]), "r"(a[tg][1]),
                                      "r"(a[tg][2]), "r"(a[tg][3]),
                                      "r"(b0), "r"(b1));
                            }
                        }
                    }
                }
            }
        }
    }
    __syncthreads();

    float blo = __ldg(&bias[oc0 + m0 + (lane >> 2)]);
    float bhi = __ldg(&bias[oc0 + m0 + (lane >> 2) + 8]);

    if (POOL) {
        float slo = 0.f, shi = 0.f;
#pragma unroll
        for (int r = 0; r < 4; r++)
#pragma unroll
            for (int nt = 0; nt < 4; nt++) {
                slo += fmaxf(acc[r][nt][0] + blo, 0.f) + fmaxf(acc[r][nt][1] + blo, 0.f);
                shi += fmaxf(acc[r][nt][2] + bhi, 0.f) + fmaxf(acc[r][nt][3] + bhi, 0.f);
            }
        slo += __shfl_xor_sync(0xffffffffu, slo, 1);
        slo += __shfl_xor_sync(0xffffffffu, slo, 2);
        shi += __shfl_xor_sync(0xffffffffu, shi, 1);
        shi += __shfl_xor_sync(0xffffffffu, shi, 2);
        if ((lane & 3) == 0) {
            atomicAdd(&pool[oc0 + m0 + (lane >> 2)], slo);
            atomicAdd(&pool[oc0 + m0 + (lane >> 2) + 8], shi);
        }
    } else {
        __nv_bfloat16* sOut = (__nv_bfloat16*)smW;   // weights no longer needed
#pragma unroll
        for (int r = 0; r < 4; r++) {
            if (r) __syncthreads();
#pragma unroll
            for (int nt = 0; nt < 4; nt++) {
                int px = nb + nt * 8 + (lane & 3) * 2;
                int oc = m0 + (lane >> 2);
                sOut[px * 64 + oc]           = __float2bfloat16(fmaxf(acc[r][nt][0] + blo, 0.f));
                sOut[(px + 1) * 64 + oc]     = __float2bfloat16(fmaxf(acc[r][nt][1] + blo, 0.f));
                sOut[px * 64 + oc + 8]       = __float2bfloat16(fmaxf(acc[r][nt][2] + bhi, 0.f));
                sOut[(px + 1) * 64 + oc + 8] = __float2bfloat16(fmaxf(acc[r][nt][3] + bhi, 0.f));
            }
            __syncthreads();
            for (int idx = tid; idx < 512; idx += 256) {
                int px = idx >> 3, og = idx & 7;
                *(uint4*)(outNHWC + ((size_t)((y0 + r) * 384 + x0 + px)) * Cout + oc0 + og * 8) =
                    *(const uint4*)(sOut + px * 64 + og * 8);
            }
        }
    }
}

// ---------------- TF32 MMA implicit-GEMM 3x3 conv (branch path, pad=1) ----------------
template<int CIN, int COUT, bool INNHWC>
__global__ void __launch_bounds__(256) tf32conv_k(
    const float* __restrict__ in,
    const uint32_t* __restrict__ wfrag,
    const float* __restrict__ bias,
    float* __restrict__ outNHWC,
    const int* __restrict__ selp, int selv)
{
    if (__ldg(selp) != selv) return;
    constexpr int MS = COUT / 16;
    constexpr int NS = 8 / MS;
    constexpr int NT = 8 / NS;
    constexpr int WCNT = 3 * MS * 2 * 32 * 4;

    const int tid  = threadIdx.x;
    const int lane = tid & 31, warp = tid >> 5;
    const int x0 = blockIdx.x * 64;
    const int y0 = blockIdx.y * 4;
    const int b  = blockIdx.z;
    const int m0 = (warp % MS) * 16;
    const int nb = (warp / MS) * (64 / NS);

    const float* inb = in + (size_t)b * CIN * HWsz;
    float* outb = outNHWC + (size_t)b * HWsz * COUT;

    __shared__ uint32_t sIn[6 * 66 * 20];
    __shared__ __align__(16) uint32_t sW[3 * 4 * 2 * 32 * 4];

    float acc[4][NT][4];
#pragma unroll
    for (int r = 0; r < 4; r++)
#pragma unroll
        for (int nt = 0; nt < NT; nt++)
#pragma unroll
            for (int c = 0; c < 4; c++) acc[r][nt][c] = 0.f;

    const int KC = CIN / 16;
    for (int kc = 0; kc < KC; kc++) {
        __syncthreads();
        for (int idx = tid; idx < 6336; idx += 256) {
            int cc, dy, px;
            if (INNHWC) { cc = idx & 15; int t = idx >> 4; px = t % 66; dy = t / 66; }
            else        { cc = idx / 396; int rem = idx - cc * 396; dy = rem / 66; px = rem - dy * 66; }
            int gy = y0 + dy - 1, gx = x0 - 1 + px;
            float v = 0.f;
            if ((unsigned)gy < 384u && (unsigned)gx < 384u)
                v = INNHWC ? inb[(size_t)(gy * 384 + gx) * CIN + kc * 16 + cc]
                           : inb[(size_t)(kc * 16 + cc) * HWsz + gy * 384 + gx];
            uint32_t u;
            asm("cvt.rna.tf32.f32 %0, %1;" : "=r"(u) : "f"(v));
            sIn[(dy * 66 + px) * 20 + cc] = u;
        }
        const uint4* wsrc = (const uint4*)(wfrag + (size_t)kc * 9 * MS * 2 * 32 * 4);
#pragma unroll
        for (int tg = 0; tg < 3; tg++) {
            if (tg) __syncthreads();
            for (int idx = tid; idx < WCNT / 4; idx += 256)
                ((uint4*)sW)[idx] = wsrc[tg * (WCNT / 4) + idx];
            __syncthreads();
#pragma unroll
            for (int tt = 0; tt < 3; tt++) {
#pragma unroll
                for (int k8 = 0; k8 < 2; k8++) {
                    uint4 af = *(const uint4*)&sW[(((tt * MS + (m0 >> 4)) * 2 + k8) * 32 + lane) * 4];
#pragma unroll
                    for (int r = 0; r < 4; r++) {
                        int wbase = ((tg + r) * 66 + nb + (lane >> 2) + tt) * 20 + k8 * 8 + (lane & 3);
#pragma unroll
                        for (int nt = 0; nt < NT; nt++) {
                            uint32_t b0 = sIn[wbase + nt * 160];
                            uint32_t b1 = sIn[wbase + nt * 160 + 4];
                            asm volatile(
                                "mma.sync.aligned.m16n8k8.row.col.f32.tf32.tf32.f32 "
                                "{%0,%1,%2,%3},{%4,%5,%6,%7},{%8,%9},{%0,%1,%2,%3};\n"
                                : "+f"(acc[r][nt][0]), "+f"(acc[r][nt][1]),
                                  "+f"(acc[r][nt][2]), "+f"(acc[r][nt][3])
                                : "r"(af.x), "r"(af.y), "r"(af.z), "r"(af.w),
                                  "r"(b0), "r"(b1));
                        }
                    }
                }
            }
        }
    }
    __syncthreads();

    float blo = __ldg(&bias[m0 + (lane >> 2)]);
    float bhi = __ldg(&bias[m0 + (lane >> 2) + 8]);

    float* sOut = (float*)sIn;
#pragma unroll
    for (int r = 0; r < 4; r++) {
        if (r) __syncthreads();
#pragma unroll
        for (int nt = 0; nt < NT; nt++) {
            int px = nb + nt * 8 + (lane & 3) * 2;
            int oc = m0 + (lane >> 2);
            sOut[px * COUT + oc]           = fmaxf(acc[r][nt][0] + blo, 0.f);
            sOut[(px + 1) * COUT + oc]     = fmaxf(acc[r][nt][1] + blo, 0.f);
            sOut[px * COUT + oc + 8]       = fmaxf(acc[r][nt][2] + bhi, 0.f);
            sOut[(px + 1) * COUT + oc + 8] = fmaxf(acc[r][nt][3] + bhi, 0.f);
        }
        __syncthreads();
        for (int idx = tid; idx < 16 * COUT; idx += 256) {
            int px = idx / (COUT / 4), og = idx % (COUT / 4);
            *(float4*)(outb + (size_t)((y0 + r) * 384 + x0 + px) * COUT + og * 4) =
                *(const float4*)(sOut + px * COUT + og * 4);
        }
    }
}

// ---------------- logits + argmax ----------------
__global__ void logits_k(const float* __restrict__ fcw, const float* __restrict__ fcb) {
    __shared__ float l[3];
    int t = threadIdx.x;
    if (t < 3) {
        float s = 0.f;
        const float inv = 1.0f / (float)HWsz;
        for (int k = 0; k < 256; k++)
            s = fmaf(fcw[t * 256 + k], g_pool[k] * inv, s);
        l[t] = s + fcb[t];
    }
    __syncthreads();
    if (t == 0) {
        int best = 0; float bv = l[0];
        if (l[1] > bv) { bv = l[1]; best = 1; }
        if (l[2] > bv) { bv = l[2]; best = 2; }
        g_sel[0] = best;
    }
}

// ---------------- fused LayerNorm + 1x1 pwconv (32 -> 96), dual src layout ----------------
__global__ void __launch_bounds__(128) ln_pw_k(
    const float* __restrict__ x,
    const float* __restrict__ lnw, const float* __restrict__ lnb,
    const float* __restrict__ pww)
{
    __shared__ float s_w[96 * 32];
    __shared__ float s_lw[32], s_lb[32];
    int tid = threadIdx.x;
    for (int i = tid; i < 96 * 32; i += 128) s_w[i] = pww[i];
    if (tid < 32) { s_lw[tid] = lnw[tid]; s_lb[tid] = lnb[tid]; }
    __syncthreads();
    const int sel = __ldg(g_sel);

    size_t pair = (size_t)blockIdx.x * 128 + tid;
    size_t gp = pair * 2;
    int b = (int)(gp / HWsz);
    int p = (int)(gp % HWsz);

    float a0[32], a1[32];
    if (sel == 0) {
#pragma unroll
        for (int c = 0; c < 32; c++) {
            float2 v = *(const float2*)&x[(size_t)(b * 32 + c) * HWsz + p];
            a0[c] = v.x; a1[c] = v.y;
        }
    } else {
        const float4* r0 = (const float4*)&g_xb[((size_t)b * HWsz + p) * 32];
        const float4* r1 = (const float4*)&g_xb[((size_t)b * HWsz + p + 1) * 32];
#pragma unroll
        for (int q = 0; q < 8; q++) {
            float4 v0 = r0[q], v1 = r1[q];
            a0[q * 4] = v0.x; a0[q * 4 + 1] = v0.y; a0[q * 4 + 2] = v0.z; a0[q * 4 + 3] = v0.w;
            a1[q * 4] = v1.x; a1[q * 4 + 1] = v1.y; a1[q * 4 + 2] = v1.z; a1[q * 4 + 3] = v1.w;
        }
    }
    float m0 = 0.f, m1 = 0.f;
#pragma unroll
    for (int c = 0; c < 32; c++) { m0 += a0[c]; m1 += a1[c]; }
    m0 *= (1.f / 32.f); m1 *= (1.f / 32.f);
    float v0 = 0.f, v1 = 0.f;
#pragma unroll
    for (int c = 0; c < 32; c++) {
        float d0 = a0[c] - m0, d1 = a1[c] - m1;
        v0 = fmaf(d0, d0, v0); v1 = fmaf(d1, d1, v1);
    }
    float r0 = rsqrtf(v0 * (1.f / 32.f) + 1e-6f);
    float r1 = rsqrtf(v1 * (1.f / 32.f) + 1e-6f);
#pragma unroll
    for (int c = 0; c < 32; c++) {
        a0[c] = fmaf((a0[c] - m0) * r0, s_lw[c], s_lb[c]);
        a1[c] = fmaf((a1[c] - m1) * r1, s_lw[c], s_lb[c]);
    }
    for (int oc = 0; oc < 96; oc++) {
        float acc0 = 0.f, acc1 = 0.f;
#pragma unroll
        for (int c = 0; c < 32; c++) {
            float w = s_w[oc * 32 + c];
            acc0 = fmaf(w, a0[c], acc0);
            acc1 = fmaf(w, a1[c], acc1);
        }
        float2 o; o.x = acc0; o.y = acc1;
        *(float2*)&g_qkv_pre[(size_t)(b * 96 + oc) * HWsz + p] = o;
    }
}

// ---------------- depthwise 3x3, 4 px/thread, optional gelu ----------------
__global__ void dw4_k(const float* __restrict__ in, const float* __restrict__ w,
                      float* __restrict__ out, int Cn, int doGelu, int totalQuads)
{
    int idx = blockIdx.x * 256 + threadIdx.x;
    if (idx >= totalQuads) return;
    int plane = idx / 36864;
    int q = idx - plane * 36864;
    int y = q / 96, qx = q - y * 96;
    int x0 = qx * 4;
    int c = plane % Cn;
    const float* ip = in + (size_t)plane * HWsz;
    const float* wp = w + c * 9;
    float wr[9];
#pragma unroll
    for (int t = 0; t < 9; t++) wr[t] = __ldg(&wp[t]);
    float o[4] = {0.f, 0.f, 0.f, 0.f};
    if (y >= 1 && y <= 382 && qx >= 1 && qx <= 94) {
#pragma unroll
        for (int dy = 0; dy < 3; dy++) {
            const float* row = ip + (size_t)(y + dy - 1) * Ww + x0;
            float l = row[-1];
            float4 m = *(const float4*)row;
            float rr = row[4];
            float w0 = wr[dy * 3], w1 = wr[dy * 3 + 1], w2 = wr[dy * 3 + 2];
            o[0] = fmaf(w0, l,   fmaf(w1, m.x, fmaf(w2, m.y, o[0])));
            o[1] = fmaf(w0, m.x, fmaf(w1, m.y, fmaf(w2, m.z, o[1])));
            o[2] = fmaf(w0, m.y, fmaf(w1, m.z, fmaf(w2, m.w, o[2])));
            o[3] = fmaf(w0, m.z, fmaf(w1, m.w, fmaf(w2, rr,  o[3])));
        }
    } else {
#pragma unroll
        for (int j = 0; j < 4; j++) {
            int x = x0 + j;
            float s = 0.f;
#pragma unroll
            for (int dy = 0; dy < 3; dy++) {
                int yy = y + dy - 1;
                if (yy < 0 || yy >= Hh) continue;
#pragma unroll
                for (int dx = 0; dx < 3; dx++) {
                    int xx = x + dx - 1;
                    if (xx < 0 || xx >= Ww) continue;
                    s = fmaf(wr[dy * 3 + dx], ip[(size_t)yy * Ww + xx], s);
                }
            }
            o[j] = s;
        }
    }
    if (doGelu) {
#pragma unroll
        for (int j = 0; j < 4; j++) o[j] = gelu_exact(o[j]);
    }
    *(float4*)(out + (size_t)plane * HWsz + (size_t)y * Ww + x0) = make_float4(o[0], o[1], o[2], o[3]);
}

// ---------------- fused sumsq + gram, atomic accumulate ----------------
__global__ void __launch_bounds__(256) sg_k() {
    int bid = blockIdx.x;
    int chunk = bid & 15, h = (bid >> 4) & 7, b = bid >> 7;
    const float* qp = g_qkv + (size_t)(b * 96 + h * 4) * HWsz;
    const float* kp = g_qkv + (size_t)(b * 96 + 32 + h * 4) * HWsz;
    float acc[24];
#pragma unroll
    for (int v = 0; v < 24; v++) acc[v] = 0.f;
    int i0 = chunk * 9216;
    for (int i = i0 + threadIdx.x; i < i0 + 9216; i += 256) {
        float qv[4], kv[4];
#pragma unroll
        for (int c = 0; c < 4; c++) {
            qv[c] = qp[(size_t)c * HWsz + i];
            kv[c] = kp[(size_t)c * HWsz + i];
        }
#pragma unroll
        for (int c = 0; c < 4; c++) {
            acc[16 + c] = fmaf(qv[c], qv[c], acc[16 + c]);
            acc[20 + c] = fmaf(kv[c], kv[c], acc[20 + c]);
#pragma unroll
            for (int d = 0; d < 4; d++)
                acc[c * 4 + d] = fmaf(qv[c], kv[d], acc[c * 4 + d]);
        }
    }
#pragma unroll
    for (int v = 0; v < 24; v++)
#pragma unroll
        for (int off = 16; off; off >>= 1)
            acc[v] += __shfl_down_sync(0xffffffffu, acc[v], off);
    __shared__ float sh[8][24];
    int warp = threadIdx.x >> 5, lane = threadIdx.x & 31;
    if (lane == 0)
#pragma unroll
        for (int v = 0; v < 24; v++) sh[warp][v] = acc[v];
    __syncthreads();
    if (threadIdx.x < 24) {
        float s = 0.f;
#pragma unroll
        for (int wq = 0; wq < 8; wq++) s += sh[wq][threadIdx.x];
        int v = threadIdx.x;
        if (v < 16)      atomicAdd(&g_S[(b * 8 + h) * 16 + v], s);
        else if (v < 20) atomicAdd(&g_ssq[b * 32 + h * 4 + (v - 16)], s);
        else             atomicAdd(&g_ssq[128 + b * 32 + h * 4 + (v - 20)], s);
    }
}

// ---------------- normalize + temperature + softmax ----------------
__global__ void attn_k(const float* __restrict__ temp) {
    int t = threadIdx.x;
    if (t >= 32) return;
    int b = t >> 3, h = t & 7;
    float nq[4], nk[4];
#pragma unroll
    for (int c = 0; c < 4; c++) {
        nq[c] = fmaxf(sqrtf(g_ssq[b * 32 + h * 4 + c]), 1e-12f);
        nk[c] = fmaxf(sqrtf(g_ssq[128 + b * 32 + h * 4 + c]), 1e-12f);
    }
    float tp = temp[h];
    float A[16];
#pragma unroll
    for (int c = 0; c < 4; c++)
#pragma unroll
        for (int d = 0; d < 4; d++)
            A[c * 4 + d] = g_S[(b * 8 + h) * 16 + c * 4 + d] / (nq[c] * nk[d]) * tp;
#pragma unroll
    for (int c = 0; c < 4; c++) {
        float m = A[c * 4];
#pragma unroll
        for (int d = 1; d < 4; d++) m = fmaxf(m, A[c * 4 + d]);
        float sum = 0.f;
#pragma unroll
        for (int d = 0; d < 4; d++) { A[c * 4 + d] = expf(A[c * 4 + d] - m); sum += A[c * 4 + d]; }
        float inv = 1.f / sum;
#pragma unroll
        for (int d = 0; d < 4; d++) g_attn[(b * 8 + h) * 16 + c * 4 + d] = A[c * 4 + d] * inv;
    }
}

// ---------------- fused: attn@v -> proj -> +res -> ff1 -> gelu, dual res layout ----------------
__global__ void __launch_bounds__(128) outproj_k(
    const float* __restrict__ x,
    const float* __restrict__ projw, const float* __restrict__ ff1w)
{
    __shared__ float s_at[128], s_pw[1024], s_fw[1024];
    int b = blockIdx.z;
    int tid = threadIdx.x;
    for (int i = tid; i < 1024; i += 128) { s_pw[i] = projw[i]; s_fw[i] = ff1w[i]; }
    if (tid < 128) s_at[tid] = g_attn[b * 128 + tid];
    __syncthreads();
    const int sel = __ldg(g_sel);

    int p = blockIdx.x * 128 + tid;
    float v[32];
#pragma unroll
    for (int c = 0; c < 32; c++)
        v[c] = g_qkv[(size_t)(b * 96 + 64 + c) * HWsz + p];
    float o[32];
#pragma unroll
    for (int c = 0; c < 32; c++) {
        int h = c >> 2, ci = c & 3;
        const float* at = &s_at[h * 16 + ci * 4];
        int vb = c & ~3;
        o[c] = at[0] * v[vb] + at[1] * v[vb + 1] + at[2] * v[vb + 2] + at[3] * v[vb + 3];
    }
    float resv[32];
    if (sel == 0) {
#pragma unroll
        for (int c = 0; c < 32; c++)
            resv[c] = x[(size_t)(b * 32 + c) * HWsz + p];
    } else {
        const float4* rp = (const float4*)&g_xb[((size_t)b * HWsz + p) * 32];
#pragma unroll
        for (int q = 0; q < 8; q++) {
            float4 vv = rp[q];
            resv[q * 4] = vv.x; resv[q * 4 + 1] = vv.y; resv[q * 4 + 2] = vv.z; resv[q * 4 + 3] = vv.w;
        }
    }
    float y[32];
#pragma unroll
    for (int c = 0; c < 32; c++) {
        float acc = resv[c];
#pragma unroll
        for (int c2 = 0; c2 < 32; c2++)
            acc = fmaf(s_pw[c * 32 + c2], o[c2], acc);
        y[c] = acc;
    }
#pragma unroll
    for (int c = 0; c < 32; c++) {
        float acc = 0.f;
#pragma unroll
        for (int c2 = 0; c2 < 32; c2++)
            acc = fmaf(s_fw[c * 32 + c2], y[c2], acc);
        g_ff[(size_t)(b * 32 + c) * HWsz + p] = gelu_exact(acc);
    }
}

// ---------------- launch ----------------
extern "C" void kernel_launch(void* const* d_in, const int* in_sizes, int n_in,
                              void* d_out, int out_size)
{
    const float* x       = (const float*)d_in[0];
    const float* ln_w    = (const float*)d_in[1];
    const float* ln_b    = (const float*)d_in[2];
    const float* temper  = (const float*)d_in[3];
    const float* pw_w    = (const float*)d_in[4];
    const float* dw_w    = (const float*)d_in[5];
    const float* proj_w  = (const float*)d_in[6];
    const float* ff1_w   = (const float*)d_in[7];
    const float* ffdw_w  = (const float*)d_in[8];
    const float* det_w1  = (const float*)d_in[9];
    const float* det_b1  = (const float*)d_in[10];
    const float* det_w2  = (const float*)d_in[11];
    const float* det_b2  = (const float*)d_in[12];
    const float* det_w3  = (const float*)d_in[13];
    const float* det_b3  = (const float*)d_in[14];
    const float* det_fcw = (const float*)d_in[15];
    const float* det_fcb = (const float*)d_in[16];
    const float* hvi_w1  = (const float*)d_in[17];
    const float* hvi_b1  = (const float*)d_in[18];
    const float* hvi_w2  = (const float*)d_in[19];
    const float* hvi_b2  = (const float*)d_in[20];
    const float* ycc_w1  = (const float*)d_in[21];
    const float* ycc_b1  = (const float*)d_in[22];
    const float* ycc_w2  = (const float*)d_in[23];
    const float* ycc_b2  = (const float*)d_in[24];
    float* outp = (float*)d_out;

    float *p_t64, *p_pool, *p_xb, *p_qkv_pre, *p_qkv, *p_ff;
    int* p_sel;
    __nv_bfloat16 *p_xh, *p_det1h, *p_det2h, *p_wbf1, *p_wbf2, *p_wbf3;
    uint32_t* p_wt32;
    cudaGetSymbolAddress((void**)&p_t64, g_t64);
    cudaGetSymbolAddress((void**)&p_pool, g_pool);
    cudaGetSymbolAddress((void**)&p_sel,  g_sel);
    cudaGetSymbolAddress((void**)&p_xb,   g_xb);
    cudaGetSymbolAddress((void**)&p_qkv_pre, g_qkv_pre);
    cudaGetSymbolAddress((void**)&p_qkv,  g_qkv);
    cudaGetSymbolAddress((void**)&p_ff,   g_ff);
    cudaGetSymbolAddress((void**)&p_xh,   g_xh);
    cudaGetSymbolAddress((void**)&p_det1h, g_det1h);
    cudaGetSymbolAddress((void**)&p_det2h, g_det2h);
    cudaGetSymbolAddress((void**)&p_wbf1, g_wbf1);
    cudaGetSymbolAddress((void**)&p_wbf2, g_wbf2);
    cudaGetSymbolAddress((void**)&p_wbf3, g_wbf3);
    cudaGetSymbolAddress((void**)&p_wt32, g_wt32);

    // allow 77760 B dynamic smem on the detector convs (host attr call; not a stream op)
    const int DSM = 31680 + 46080;
    cudaFuncSetAttribute(mmaconvW_k<32,  false>, cudaFuncAttributeMaxDynamicSharedMemorySize, DSM);
    cudaFuncSetAttribute(mmaconvW_k<64,  false>, cudaFuncAttributeMaxDynamicSharedMemorySize, DSM);
    cudaFuncSetAttribute(mmaconvW_k<128, true >, cudaFuncAttributeMaxDynamicSharedMemorySize, DSM);

    // setup
    cvtz_k<<<(18432 + 73728 + 294912 + 512 + 4 * 18432 + 255) / 256, 256>>>(
        det_w1, det_w2, det_w3, hvi_w1, hvi_w2, ycc_w1, ycc_w2);
    cvt_x_k<<<HWsz / 32, dim3(32, 32)>>>(x);

    // detector (batch 0, bf16 HMMA, all-taps-resident); 4th launch = mmaconvW<64> (ncu target)
    mmaconvW_k<32,  false><<<dim3(6, 96, 1), 256, DSM>>>(p_xh,    p_wbf1, det_b1, p_det1h, nullptr, 64);
    mmaconvW_k<64,  false><<<dim3(6, 96, 2), 256, DSM>>>(p_det1h, p_wbf2, det_b2, p_det2h, nullptr, 128);
    mmaconvW_k<128, true ><<<dim3(6, 96, 4), 256, DSM>>>(p_det2h, p_wbf3, det_b3, nullptr, p_pool, 256);
    logits_k<<<1, 32>>>(det_fcw, det_fcb);

    // branch (TF32 MMA, NHWC output; predicated on g_sel)
    tf32conv_k<32, 64, false><<<dim3(6, 96, 4), 256>>>(x,     p_wt32 + 0 * 18432, hvi_b1, p_t64, p_sel, 1);
    tf32conv_k<64, 32, true ><<<dim3(6, 96, 4), 256>>>(p_t64, p_wt32 + 1 * 18432, hvi_b2, p_xb,  p_sel, 1);
    tf32conv_k<32, 64, false><<<dim3(6, 96, 4), 256>>>(x,     p_wt32 + 2 * 18432, ycc_b1, p_t64, p_sel, 2);
    tf32conv_k<64, 32, true ><<<dim3(6, 96, 4), 256>>>(p_t64, p_wt32 + 3 * 18432, ycc_b2, p_xb,  p_sel, 2);

    // LN + pw 1x1
    ln_pw_k<<<(NB * HWsz / 2) / 128, 128>>>(x, ln_w, ln_b, pw_w);
    // depthwise 3x3 (96 ch)
    dw4_k<<<(NB * 96 * 36864 + 255) / 256, 256>>>(p_qkv_pre, dw_w, p_qkv, 96, 0, NB * 96 * 36864);
    // fused sumsq + gram
    sg_k<<<512, 256>>>();
    attn_k<<<1, 32>>>(temper);
    // attn apply + proj + residual + ff1 + gelu
    outproj_k<<<dim3(HWsz / 128, 1, NB), 128>>>(x, proj_w, ff1_w);
    // ffdw depthwise + gelu -> out
    dw4_k<<<(NB * 32 * 36864 + 255) / 256, 256>>>(p_ff, ffdw_w, outp, 32, 1, NB * 32 * 36864);

    (void)in_sizes; (void)n_in; (void)out_size;
}

// round 17
// speedup vs baseline: 1.1325x; 1.0332x over previous
#include <cuda_runtime.h>
#include <cuda_bf16.h>
#include <cstdint>
#include <math.h>

#define Hh 384
#define Ww 384
#define HWsz 147456
#define NB 4

// ---------------- static device scratch ----------------
static __device__ float g_t64[(size_t)NB * 64 * HWsz];    // branch layer1 out, NHWC fp32
static __device__ float g_pool[256];
static __device__ int   g_sel[1];
static __device__ float g_xb[(size_t)NB * 32 * HWsz];     // branch out, NHWC fp32 (sel!=0)
static __device__ float g_qkv_pre[(size_t)NB * 96 * HWsz];
static __device__ float g_qkv[(size_t)NB * 96 * HWsz];
static __device__ float g_ssq[256];
static __device__ float g_S[512];
static __device__ float g_attn[512];
static __device__ float g_ff[(size_t)NB * 32 * HWsz];

// bf16 detector path (batch 0 only)
static __device__ __nv_bfloat16 g_xh[(size_t)HWsz * 32];
static __device__ __nv_bfloat16 g_det1h[(size_t)HWsz * 64];
static __device__ __nv_bfloat16 g_det2h[(size_t)HWsz * 128];
static __device__ __nv_bfloat16 g_wbf1[9 * 64 * 40];
static __device__ __nv_bfloat16 g_wbf2[2 * 2 * 9 * 64 * 40];
static __device__ __nv_bfloat16 g_wbf3[4 * 4 * 9 * 64 * 40];

// tf32 fragment-major branch weights: [0]=hvi1 [1]=hvi2 [2]=ycc1 [3]=ycc2
static __device__ uint32_t g_wt32[4][18432];

__device__ __forceinline__ float gelu_exact(float x) {
    return 0.5f * x * (1.0f + erff(x * 0.70710678118654752f));
}

// ---------------- merged weight-convert + zero kernel ----------------
__device__ __forceinline__ void cvt_one(const float* w, __nv_bfloat16* dst, int CIN, int idx) {
    int ocg = idx / (CIN * 9);
    int rem = idx - ocg * (CIN * 9);
    int cin = rem / 9, tap = rem % 9;
    int ot = ocg >> 6, oc = ocg & 63;
    int kc = cin >> 5, c = cin & 31;
    dst[((((size_t)ot * (CIN / 32) + kc) * 9 + tap) * 64 + oc) * 40 + c] = __float2bfloat16(w[idx]);
}
// tf32 fragment-major: dst[(((kc*9+tap)*MS + ms)*2 + k8)*32 + lane]*4 + reg
__device__ __forceinline__ void cvt_t32(const float* w, uint32_t* dst, int CIN, int MS, int idx) {
    int oc = idx / (CIN * 9);
    int rem = idx - oc * (CIN * 9);
    int cin = rem / 9, tap = rem % 9;
    int kc = cin >> 4, kk = cin & 15, k8 = kk >> 3, k4 = kk & 7;
    int reg  = ((oc >> 3) & 1) | ((k4 >> 2) << 1);
    int lane = (oc & 7) * 4 + (k4 & 3);
    int ms   = oc >> 4;
    uint32_t u;
    asm("cvt.rna.tf32.f32 %0, %1;" : "=r"(u) : "f"(w[idx]));
    dst[((((kc * 9 + tap) * MS + ms) * 2 + k8) * 32 + lane) * 4 + reg] = u;
}
__global__ void cvtz_k(const float* __restrict__ w1, const float* __restrict__ w2,
                       const float* __restrict__ w3,
                       const float* __restrict__ h1, const float* __restrict__ h2,
                       const float* __restrict__ y1, const float* __restrict__ y2)
{
    int idx = blockIdx.x * 256 + threadIdx.x;
    if (idx < 18432) { cvt_one(w1, g_wbf1, 32, idx); return; }
    idx -= 18432;
    if (idx < 73728) { cvt_one(w2, g_wbf2, 64, idx); return; }
    idx -= 73728;
    if (idx < 294912) { cvt_one(w3, g_wbf3, 128, idx); return; }
    idx -= 294912;
    if (idx < 512) {
        if (idx < 256) { g_pool[idx] = 0.f; g_ssq[idx] = 0.f; }
        g_S[idx] = 0.f;
        return;
    }
    idx -= 512;
    if (idx < 18432) { cvt_t32(h1, g_wt32[0], 32, 4, idx); return; }
    idx -= 18432;
    if (idx < 18432) { cvt_t32(h2, g_wt32[1], 64, 2, idx); return; }
    idx -= 18432;
    if (idx < 18432) { cvt_t32(y1, g_wt32[2], 32, 4, idx); return; }
    idx -= 18432;
    if (idx < 18432) { cvt_t32(y2, g_wt32[3], 64, 2, idx); return; }
}

// ---------------- x (fp32 NCHW b0) -> bf16 NHWC ----------------
__global__ void cvt_x_k(const float* __restrict__ x) {
    __shared__ float s[32][33];
    int p0 = blockIdx.x * 32;
    s[threadIdx.y][threadIdx.x] = x[(size_t)threadIdx.y * HWsz + p0 + threadIdx.x];
    __syncthreads();
    g_xh[(size_t)(p0 + threadIdx.y) * 32 + threadIdx.x] = __float2bfloat16(s[threadIdx.x][threadIdx.y]);
}

// ---------------- bf16 HMMA implicit-GEMM 3x3 conv, all-taps-resident (dynamic smem) ----------------
template<int CIN, bool POOL>
__global__ void __launch_bounds__(256) mmaconvW_k(
    const __nv_bfloat16* __restrict__ in,
    const __nv_bfloat16* __restrict__ wbf,
    const float* __restrict__ bias,
    __nv_bfloat16* __restrict__ outNHWC,
    float* __restrict__ pool,
    int Cout)
{
    extern __shared__ __align__(16) unsigned char smraw[];
    unsigned char* smIn = smraw;                // bf16 [(dy*66+px)*40 + c], 31680 B
    unsigned char* smW  = smraw + 31680;        // bf16 [tap(9)][oc(64)][40],  46080 B

    const int tid  = threadIdx.x;
    const int lane = tid & 31, warp = tid >> 5;
    const int x0 = blockIdx.x * 64;
    const int y0 = blockIdx.y * 4;
    const int ot = blockIdx.z;
    const int oc0 = ot * 64;
    const int m0 = (warp & 3) << 4;
    const int nb = (warp >> 2) << 5;

    const uint32_t sInBs = (uint32_t)__cvta_generic_to_shared(smIn);
    const uint32_t sWBs  = (uint32_t)__cvta_generic_to_shared(smW);

    const int mrow = m0 + (lane & 7) + ((lane >> 3) & 1) * 8;
    const int kofA = ((lane >> 4) & 1) * 8;
    const int lane15 = lane & 15;
    const int rowB = lane15 & 7;
    const int kofB = (lane15 >> 3) * 8;

    float acc[4][4][4];
#pragma unroll
    for (int r = 0; r < 4; r++)
#pragma unroll
        for (int nt = 0; nt < 4; nt++)
#pragma unroll
            for (int c = 0; c < 4; c++) acc[r][nt][c] = 0.f;

    const int KC = CIN / 32;
    for (int kc = 0; kc < KC; kc++) {
        __syncthreads();
        for (int idx = tid; idx < 1584; idx += 256) {
            int dy = idx / 264; int rem = idx - dy * 264;
            int px = rem >> 2, cg = rem & 3;
            int gy = y0 + dy - 1, gx = x0 - 1 + px;
            uint4 v = make_uint4(0u, 0u, 0u, 0u);
            if ((unsigned)gy < 384u && (unsigned)gx < 384u)
                v = *(const uint4*)(in + ((size_t)(gy * 384 + gx)) * CIN + kc * 32 + cg * 8);
            *(uint4*)(smIn + ((dy * 66 + px) * 40 + cg * 8) * 2) = v;
        }
        const uint4* wsrc = (const uint4*)(wbf + ((size_t)(ot * KC + kc) * 9) * 64 * 40);
        for (int idx = tid; idx < 2880; idx += 256)
            ((uint4*)smW)[idx] = wsrc[idx];
        __syncthreads();

#pragma unroll
        for (int tt = 0; tt < 3; tt++) {
#pragma unroll
            for (int k16 = 0; k16 < 2; k16++) {
                uint32_t a[3][4];
#pragma unroll
                for (int tg = 0; tg < 3; tg++) {
                    uint32_t aAddr = sWBs + (uint32_t)(
                        (((tg * 3 + tt) * 64 + mrow) * 40 + k16 * 16 + kofA) * 2);
                    asm volatile(
                        "ldmatrix.sync.aligned.m8n8.x4.shared.b16 {%0,%1,%2,%3}, [%4];"
                        : "=r"(a[tg][0]), "=r"(a[tg][1]), "=r"(a[tg][2]), "=r"(a[tg][3])
                        : "r"(aAddr));
                }
#pragma unroll
                for (int s = 0; s < 6; s++) {
                    uint32_t bBase = sInBs +
                        (uint32_t)(((s * 66 + nb + rowB + tt) * 40 + k16 * 16 + kofB) * 2);
#pragma unroll
                    for (int nt = 0; nt < 4; nt++) {
                        uint32_t b0, b1;
                        asm volatile(
                            "ldmatrix.sync.aligned.m8n8.x2.shared.b16 {%0,%1}, [%2];"
                            : "=r"(b0), "=r"(b1) : "r"(bBase + nt * 640u));
#pragma unroll
                        for (int tg = 0; tg < 3; tg++) {
                            int r = s - tg;
                            if (r >= 0 && r < 4) {
                                asm volatile(
                                    "mma.sync.aligned.m16n8k16.row.col.f32.bf16.bf16.f32 "
                                    "{%0,%1,%2,%3},{%4,%5,%6,%7},{%8,%9},{%0,%1,%2,%3};\n"
                                    : "+f"(acc[r][nt][0]), "+f"(acc[r][nt][1]),
                                      "+f"(acc[r][nt][2]), "+f"(acc[r][nt][3])
                                    : "r"(a[tg][0]), "r"(a[tg][1]),
                                      "r"(a[tg][2]), "r"(a[tg][3]),
                                      "r"(b0), "r"(b1));
                            }
                        }
                    }
                }
            }
        }
    }
    __syncthreads();

    float blo = __ldg(&bias[oc0 + m0 + (lane >> 2)]);
    float bhi = __ldg(&bias[oc0 + m0 + (lane >> 2) + 8]);

    if (POOL) {
        float slo = 0.f, shi = 0.f;
#pragma unroll
        for (int r = 0; r < 4; r++)
#pragma unroll
            for (int nt = 0; nt < 4; nt++) {
                slo += fmaxf(acc[r][nt][0] + blo, 0.f) + fmaxf(acc[r][nt][1] + blo, 0.f);
                shi += fmaxf(acc[r][nt][2] + bhi, 0.f) + fmaxf(acc[r][nt][3] + bhi, 0.f);
            }
        slo += __shfl_xor_sync(0xffffffffu, slo, 1);
        slo += __shfl_xor_sync(0xffffffffu, slo, 2);
        shi += __shfl_xor_sync(0xffffffffu, shi, 1);
        shi += __shfl_xor_sync(0xffffffffu, shi, 2);
        if ((lane & 3) == 0) {
            atomicAdd(&pool[oc0 + m0 + (lane >> 2)], slo);
            atomicAdd(&pool[oc0 + m0 + (lane >> 2) + 8], shi);
        }
    } else {
        __nv_bfloat16* sOut = (__nv_bfloat16*)smW;
#pragma unroll
        for (int r = 0; r < 4; r++) {
            if (r) __syncthreads();
#pragma unroll
            for (int nt = 0; nt < 4; nt++) {
                int px = nb + nt * 8 + (lane & 3) * 2;
                int oc = m0 + (lane >> 2);
                sOut[px * 64 + oc]           = __float2bfloat16(fmaxf(acc[r][nt][0] + blo, 0.f));
                sOut[(px + 1) * 64 + oc]     = __float2bfloat16(fmaxf(acc[r][nt][1] + blo, 0.f));
                sOut[px * 64 + oc + 8]       = __float2bfloat16(fmaxf(acc[r][nt][2] + bhi, 0.f));
                sOut[(px + 1) * 64 + oc + 8] = __float2bfloat16(fmaxf(acc[r][nt][3] + bhi, 0.f));
            }
            __syncthreads();
            for (int idx = tid; idx < 512; idx += 256) {
                int px = idx >> 3, og = idx & 7;
                *(uint4*)(outNHWC + ((size_t)((y0 + r) * 384 + x0 + px)) * Cout + oc0 + og * 8) =
                    *(const uint4*)(sOut + px * 64 + og * 8);
            }
        }
    }
}

// ---------------- TF32 MMA implicit-GEMM 3x3 conv, all-taps-resident (branch path) ----------------
// Same wavefront-dedup transform as mmaconvW: all 9 taps resident, B loaded once per
// input row s and reused across up to 3 tap rows. Dynamic smem.
template<int CIN, int COUT, bool INNHWC>
__global__ void __launch_bounds__(256) tf32convW_k(
    const float* __restrict__ in,
    const uint32_t* __restrict__ wfrag,
    const float* __restrict__ bias,
    float* __restrict__ outNHWC,
    const int* __restrict__ selp, int selv)
{
    if (__ldg(selp) != selv) return;
    constexpr int MS = COUT / 16;
    constexpr int NS = 8 / MS;
    constexpr int NT = 8 / NS;
    constexpr int WWORDS = 9 * MS * 2 * 32 * 4;   // all-taps weight words

    extern __shared__ __align__(16) unsigned char smraw[];
    uint32_t* sIn = (uint32_t*)smraw;             // [6*66*20] = 31680 B
    uint32_t* sW  = (uint32_t*)(smraw + 31680);   // WWORDS * 4 B

    const int tid  = threadIdx.x;
    const int lane = tid & 31, warp = tid >> 5;
    const int x0 = blockIdx.x * 64;
    const int y0 = blockIdx.y * 4;
    const int b  = blockIdx.z;
    const int m0 = (warp % MS) * 16;
    const int nb = (warp / MS) * (64 / NS);

    const float* inb = in + (size_t)b * CIN * HWsz;
    float* outb = outNHWC + (size_t)b * HWsz * COUT;

    float acc[4][NT][4];
#pragma unroll
    for (int r = 0; r < 4; r++)
#pragma unroll
        for (int nt = 0; nt < NT; nt++)
#pragma unroll
            for (int c = 0; c < 4; c++) acc[r][nt][c] = 0.f;

    const int KC = CIN / 16;
    for (int kc = 0; kc < KC; kc++) {
        __syncthreads();
        for (int idx = tid; idx < 6336; idx += 256) {
            int cc, dy, px;
            if (INNHWC) { cc = idx & 15; int t = idx >> 4; px = t % 66; dy = t / 66; }
            else        { cc = idx / 396; int rem = idx - cc * 396; dy = rem / 66; px = rem - dy * 66; }
            int gy = y0 + dy - 1, gx = x0 - 1 + px;
            float v = 0.f;
            if ((unsigned)gy < 384u && (unsigned)gx < 384u)
                v = INNHWC ? inb[(size_t)(gy * 384 + gx) * CIN + kc * 16 + cc]
                           : inb[(size_t)(kc * 16 + cc) * HWsz + gy * 384 + gx];
            uint32_t u;
            asm("cvt.rna.tf32.f32 %0, %1;" : "=r"(u) : "f"(v));
            sIn[(dy * 66 + px) * 20 + cc] = u;
        }
        // stage all 9 taps of weights for this kc
        const uint4* wsrc = (const uint4*)(wfrag + (size_t)kc * WWORDS);
        for (int idx = tid; idx < WWORDS / 4; idx += 256)
            ((uint4*)sW)[idx] = wsrc[idx];
        __syncthreads();

#pragma unroll
        for (int tt = 0; tt < 3; tt++) {
#pragma unroll
            for (int k8 = 0; k8 < 2; k8++) {
                uint4 af[3];
#pragma unroll
                for (int tg = 0; tg < 3; tg++)
                    af[tg] = *(const uint4*)&sW[((((tg * 3 + tt) * MS + (m0 >> 4)) * 2 + k8) * 32 + lane) * 4];
#pragma unroll
                for (int s = 0; s < 6; s++) {
                    int wbase = (s * 66 + nb + (lane >> 2) + tt) * 20 + k8 * 8 + (lane & 3);
#pragma unroll
                    for (int nt = 0; nt < NT; nt++) {
                        uint32_t b0 = sIn[wbase + nt * 160];
                        uint32_t b1 = sIn[wbase + nt * 160 + 4];
#pragma unroll
                        for (int tg = 0; tg < 3; tg++) {
                            int r = s - tg;
                            if (r >= 0 && r < 4) {
                                asm volatile(
                                    "mma.sync.aligned.m16n8k8.row.col.f32.tf32.tf32.f32 "
                                    "{%0,%1,%2,%3},{%4,%5,%6,%7},{%8,%9},{%0,%1,%2,%3};\n"
                                    : "+f"(acc[r][nt][0]), "+f"(acc[r][nt][1]),
                                      "+f"(acc[r][nt][2]), "+f"(acc[r][nt][3])
                                    : "r"(af[tg].x), "r"(af[tg].y), "r"(af[tg].z), "r"(af[tg].w),
                                      "r"(b0), "r"(b1));
                            }
                        }
                    }
                }
            }
        }
    }
    __syncthreads();

    float blo = __ldg(&bias[m0 + (lane >> 2)]);
    float bhi = __ldg(&bias[m0 + (lane >> 2) + 8]);

    float* sOut = (float*)sIn;
#pragma unroll
    for (int r = 0; r < 4; r++) {
        if (r) __syncthreads();
#pragma unroll
        for (int nt = 0; nt < NT; nt++) {
            int px = nb + nt * 8 + (lane & 3) * 2;
            int oc = m0 + (lane >> 2);
            sOut[px * COUT + oc]           = fmaxf(acc[r][nt][0] + blo, 0.f);
            sOut[(px + 1) * COUT + oc]     = fmaxf(acc[r][nt][1] + blo, 0.f);
            sOut[px * COUT + oc + 8]       = fmaxf(acc[r][nt][2] + bhi, 0.f);
            sOut[(px + 1) * COUT + oc + 8] = fmaxf(acc[r][nt][3] + bhi, 0.f);
        }
        __syncthreads();
        for (int idx = tid; idx < 16 * COUT; idx += 256) {
            int px = idx / (COUT / 4), og = idx % (COUT / 4);
            *(float4*)(outb + (size_t)((y0 + r) * 384 + x0 + px) * COUT + og * 4) =
                *(const float4*)(sOut + px * COUT + og * 4);
        }
    }
}

// ---------------- logits + argmax ----------------
__global__ void logits_k(const float* __restrict__ fcw, const float* __restrict__ fcb) {
    __shared__ float l[3];
    int t = threadIdx.x;
    if (t < 3) {
        float s = 0.f;
        const float inv = 1.0f / (float)HWsz;
        for (int k = 0; k < 256; k++)
            s = fmaf(fcw[t * 256 + k], g_pool[k] * inv, s);
        l[t] = s + fcb[t];
    }
    __syncthreads();
    if (t == 0) {
        int best = 0; float bv = l[0];
        if (l[1] > bv) { bv = l[1]; best = 1; }
        if (l[2] > bv) { bv = l[2]; best = 2; }
        g_sel[0] = best;
    }
}

// ---------------- fused LayerNorm + 1x1 pwconv (32 -> 96), dual src layout ----------------
__global__ void __launch_bounds__(128) ln_pw_k(
    const float* __restrict__ x,
    const float* __restrict__ lnw, const float* __restrict__ lnb,
    const float* __restrict__ pww)
{
    __shared__ float s_w[96 * 32];
    __shared__ float s_lw[32], s_lb[32];
    int tid = threadIdx.x;
    for (int i = tid; i < 96 * 32; i += 128) s_w[i] = pww[i];
    if (tid < 32) { s_lw[tid] = lnw[tid]; s_lb[tid] = lnb[tid]; }
    __syncthreads();
    const int sel = __ldg(g_sel);

    size_t pair = (size_t)blockIdx.x * 128 + tid;
    size_t gp = pair * 2;
    int b = (int)(gp / HWsz);
    int p = (int)(gp % HWsz);

    float a0[32], a1[32];
    if (sel == 0) {
#pragma unroll
        for (int c = 0; c < 32; c++) {
            float2 v = *(const float2*)&x[(size_t)(b * 32 + c) * HWsz + p];
            a0[c] = v.x; a1[c] = v.y;
        }
    } else {
        const float4* r0 = (const float4*)&g_xb[((size_t)b * HWsz + p) * 32];
        const float4* r1 = (const float4*)&g_xb[((size_t)b * HWsz + p + 1) * 32];
#pragma unroll
        for (int q = 0; q < 8; q++) {
            float4 v0 = r0[q], v1 = r1[q];
            a0[q * 4] = v0.x; a0[q * 4 + 1] = v0.y; a0[q * 4 + 2] = v0.z; a0[q * 4 + 3] = v0.w;
            a1[q * 4] = v1.x; a1[q * 4 + 1] = v1.y; a1[q * 4 + 2] = v1.z; a1[q * 4 + 3] = v1.w;
        }
    }
    float m0 = 0.f, m1 = 0.f;
#pragma unroll
    for (int c = 0; c < 32; c++) { m0 += a0[c]; m1 += a1[c]; }
    m0 *= (1.f / 32.f); m1 *= (1.f / 32.f);
    float v0 = 0.f, v1 = 0.f;
#pragma unroll
    for (int c = 0; c < 32; c++) {
        float d0 = a0[c] - m0, d1 = a1[c] - m1;
        v0 = fmaf(d0, d0, v0); v1 = fmaf(d1, d1, v1);
    }
    float r0 = rsqrtf(v0 * (1.f / 32.f) + 1e-6f);
    float r1 = rsqrtf(v1 * (1.f / 32.f) + 1e-6f);
#pragma unroll
    for (int c = 0; c < 32; c++) {
        a0[c] = fmaf((a0[c] - m0) * r0, s_lw[c], s_lb[c]);
        a1[c] = fmaf((a1[c] - m1) * r1, s_lw[c], s_lb[c]);
    }
    for (int oc = 0; oc < 96; oc++) {
        float acc0 = 0.f, acc1 = 0.f;
#pragma unroll
        for (int c = 0; c < 32; c++) {
            float w = s_w[oc * 32 + c];
            acc0 = fmaf(w, a0[c], acc0);
            acc1 = fmaf(w, a1[c], acc1);
        }
        float2 o; o.x = acc0; o.y = acc1;
        *(float2*)&g_qkv_pre[(size_t)(b * 96 + oc) * HWsz + p] = o;
    }
}

// ---------------- depthwise 3x3, 4 px/thread, optional gelu ----------------
__global__ void dw4_k(const float* __restrict__ in, const float* __restrict__ w,
                      float* __restrict__ out, int Cn, int doGelu, int totalQuads)
{
    int idx = blockIdx.x * 256 + threadIdx.x;
    if (idx >= totalQuads) return;
    int plane = idx / 36864;
    int q = idx - plane * 36864;
    int y = q / 96, qx = q - y * 96;
    int x0 = qx * 4;
    int c = plane % Cn;
    const float* ip = in + (size_t)plane * HWsz;
    const float* wp = w + c * 9;
    float wr[9];
#pragma unroll
    for (int t = 0; t < 9; t++) wr[t] = __ldg(&wp[t]);
    float o[4] = {0.f, 0.f, 0.f, 0.f};
    if (y >= 1 && y <= 382 && qx >= 1 && qx <= 94) {
#pragma unroll
        for (int dy = 0; dy < 3; dy++) {
            const float* row = ip + (size_t)(y + dy - 1) * Ww + x0;
            float l = row[-1];
            float4 m = *(const float4*)row;
            float rr = row[4];
            float w0 = wr[dy * 3], w1 = wr[dy * 3 + 1], w2 = wr[dy * 3 + 2];
            o[0] = fmaf(w0, l,   fmaf(w1, m.x, fmaf(w2, m.y, o[0])));
            o[1] = fmaf(w0, m.x, fmaf(w1, m.y, fmaf(w2, m.z, o[1])));
            o[2] = fmaf(w0, m.y, fmaf(w1, m.z, fmaf(w2, m.w, o[2])));
            o[3] = fmaf(w0, m.z, fmaf(w1, m.w, fmaf(w2, rr,  o[3])));
        }
    } else {
#pragma unroll
        for (int j = 0; j < 4; j++) {
            int x = x0 + j;
            float s = 0.f;
#pragma unroll
            for (int dy = 0; dy < 3; dy++) {
                int yy = y + dy - 1;
                if (yy < 0 || yy >= Hh) continue;
#pragma unroll
                for (int dx = 0; dx < 3; dx++) {
                    int xx = x + dx - 1;
                    if (xx < 0 || xx >= Ww) continue;
                    s = fmaf(wr[dy * 3 + dx], ip[(size_t)yy * Ww + xx], s);
                }
            }
            o[j] = s;
        }
    }
    if (doGelu) {
#pragma unroll
        for (int j = 0; j < 4; j++) o[j] = gelu_exact(o[j]);
    }
    *(float4*)(out + (size_t)plane * HWsz + (size_t)y * Ww + x0) = make_float4(o[0], o[1], o[2], o[3]);
}

// ---------------- fused sumsq + gram, atomic accumulate ----------------
__global__ void __launch_bounds__(256) sg_k() {
    int bid = blockIdx.x;
    int chunk = bid & 15, h = (bid >> 4) & 7, b = bid >> 7;
    const float* qp = g_qkv + (size_t)(b * 96 + h * 4) * HWsz;
    const float* kp = g_qkv + (size_t)(b * 96 + 32 + h * 4) * HWsz;
    float acc[24];
#pragma unroll
    for (int v = 0; v < 24; v++) acc[v] = 0.f;
    int i0 = chunk * 9216;
    for (int i = i0 + threadIdx.x; i < i0 + 9216; i += 256) {
        float qv[4], kv[4];
#pragma unroll
        for (int c = 0; c < 4; c++) {
            qv[c] = qp[(size_t)c * HWsz + i];
            kv[c] = kp[(size_t)c * HWsz + i];
        }
#pragma unroll
        for (int c = 0; c < 4; c++) {
            acc[16 + c] = fmaf(qv[c], qv[c], acc[16 + c]);
            acc[20 + c] = fmaf(kv[c], kv[c], acc[20 + c]);
#pragma unroll
            for (int d = 0; d < 4; d++)
                acc[c * 4 + d] = fmaf(qv[c], kv[d], acc[c * 4 + d]);
        }
    }
#pragma unroll
    for (int v = 0; v < 24; v++)
#pragma unroll
        for (int off = 16; off; off >>= 1)
            acc[v] += __shfl_down_sync(0xffffffffu, acc[v], off);
    __shared__ float sh[8][24];
    int warp = threadIdx.x >> 5, lane = threadIdx.x & 31;
    if (lane == 0)
#pragma unroll
        for (int v = 0; v < 24; v++) sh[warp][v] = acc[v];
    __syncthreads();
    if (threadIdx.x < 24) {
        float s = 0.f;
#pragma unroll
        for (int wq = 0; wq < 8; wq++) s += sh[wq][threadIdx.x];
        int v = threadIdx.x;
        if (v < 16)      atomicAdd(&g_S[(b * 8 + h) * 16 + v], s);
        else if (v < 20) atomicAdd(&g_ssq[b * 32 + h * 4 + (v - 16)], s);
        else             atomicAdd(&g_ssq[128 + b * 32 + h * 4 + (v - 20)], s);
    }
}

// ---------------- normalize + temperature + softmax ----------------
__global__ void attn_k(const float* __restrict__ temp) {
    int t = threadIdx.x;
    if (t >= 32) return;
    int b = t >> 3, h = t & 7;
    float nq[4], nk[4];
#pragma unroll
    for (int c = 0; c < 4; c++) {
        nq[c] = fmaxf(sqrtf(g_ssq[b * 32 + h * 4 + c]), 1e-12f);
        nk[c] = fmaxf(sqrtf(g_ssq[128 + b * 32 + h * 4 + c]), 1e-12f);
    }
    float tp = temp[h];
    float A[16];
#pragma unroll
    for (int c = 0; c < 4; c++)
#pragma unroll
        for (int d = 0; d < 4; d++)
            A[c * 4 + d] = g_S[(b * 8 + h) * 16 + c * 4 + d] / (nq[c] * nk[d]) * tp;
#pragma unroll
    for (int c = 0; c < 4; c++) {
        float m = A[c * 4];
#pragma unroll
        for (int d = 1; d < 4; d++) m = fmaxf(m, A[c * 4 + d]);
        float sum = 0.f;
#pragma unroll
        for (int d = 0; d < 4; d++) { A[c * 4 + d] = expf(A[c * 4 + d] - m); sum += A[c * 4 + d]; }
        float inv = 1.f / sum;
#pragma unroll
        for (int d = 0; d < 4; d++) g_attn[(b * 8 + h) * 16 + c * 4 + d] = A[c * 4 + d] * inv;
    }
}

// ---------------- fused: attn@v -> proj -> +res -> ff1 -> gelu, dual res layout ----------------
__global__ void __launch_bounds__(128) outproj_k(
    const float* __restrict__ x,
    const float* __restrict__ projw, const float* __restrict__ ff1w)
{
    __shared__ float s_at[128], s_pw[1024], s_fw[1024];
    int b = blockIdx.z;
    int tid = threadIdx.x;
    for (int i = tid; i < 1024; i += 128) { s_pw[i] = projw[i]; s_fw[i] = ff1w[i]; }
    if (tid < 128) s_at[tid] = g_attn[b * 128 + tid];
    __syncthreads();
    const int sel = __ldg(g_sel);

    int p = blockIdx.x * 128 + tid;
    float v[32];
#pragma unroll
    for (int c = 0; c < 32; c++)
        v[c] = g_qkv[(size_t)(b * 96 + 64 + c) * HWsz + p];
    float o[32];
#pragma unroll
    for (int c = 0; c < 32; c++) {
        int h = c >> 2, ci = c & 3;
        const float* at = &s_at[h * 16 + ci * 4];
        int vb = c & ~3;
        o[c] = at[0] * v[vb] + at[1] * v[vb + 1] + at[2] * v[vb + 2] + at[3] * v[vb + 3];
    }
    float resv[32];
    if (sel == 0) {
#pragma unroll
        for (int c = 0; c < 32; c++)
            resv[c] = x[(size_t)(b * 32 + c) * HWsz + p];
    } else {
        const float4* rp = (const float4*)&g_xb[((size_t)b * HWsz + p) * 32];
#pragma unroll
        for (int q = 0; q < 8; q++) {
            float4 vv = rp[q];
            resv[q * 4] = vv.x; resv[q * 4 + 1] = vv.y; resv[q * 4 + 2] = vv.z; resv[q * 4 + 3] = vv.w;
        }
    }
    float y[32];
#pragma unroll
    for (int c = 0; c < 32; c++) {
        float acc = resv[c];
#pragma unroll
        for (int c2 = 0; c2 < 32; c2++)
            acc = fmaf(s_pw[c * 32 + c2], o[c2], acc);
        y[c] = acc;
    }
#pragma unroll
    for (int c = 0; c < 32; c++) {
        float acc = 0.f;
#pragma unroll
        for (int c2 = 0; c2 < 32; c2++)
            acc = fmaf(s_fw[c * 32 + c2], y[c2], acc);
        g_ff[(size_t)(b * 32 + c) * HWsz + p] = gelu_exact(acc);
    }
}

// ---------------- launch ----------------
extern "C" void kernel_launch(void* const* d_in, const int* in_sizes, int n_in,
                              void* d_out, int out_size)
{
    const float* x       = (const float*)d_in[0];
    const float* ln_w    = (const float*)d_in[1];
    const float* ln_b    = (const float*)d_in[2];
    const float* temper  = (const float*)d_in[3];
    const float* pw_w    = (const float*)d_in[4];
    const float* dw_w    = (const float*)d_in[5];
    const float* proj_w  = (const float*)d_in[6];
    const float* ff1_w   = (const float*)d_in[7];
    const float* ffdw_w  = (const float*)d_in[8];
    const float* det_w1  = (const float*)d_in[9];
    const float* det_b1  = (const float*)d_in[10];
    const float* det_w2  = (const float*)d_in[11];
    const float* det_b2  = (const float*)d_in[12];
    const float* det_w3  = (const float*)d_in[13];
    const float* det_b3  = (const float*)d_in[14];
    const float* det_fcw = (const float*)d_in[15];
    const float* det_fcb = (const float*)d_in[16];
    const float* hvi_w1  = (const float*)d_in[17];
    const float* hvi_b1  = (const float*)d_in[18];
    const float* hvi_w2  = (const float*)d_in[19];
    const float* hvi_b2  = (const float*)d_in[20];
    const float* ycc_w1  = (const float*)d_in[21];
    const float* ycc_b1  = (const float*)d_in[22];
    const float* ycc_w2  = (const float*)d_in[23];
    const float* ycc_b2  = (const float*)d_in[24];
    float* outp = (float*)d_out;

    float *p_t64, *p_pool, *p_xb, *p_qkv_pre, *p_qkv, *p_ff;
    int* p_sel;
    __nv_bfloat16 *p_xh, *p_det1h, *p_det2h, *p_wbf1, *p_wbf2, *p_wbf3;
    uint32_t* p_wt32;
    cudaGetSymbolAddress((void**)&p_t64, g_t64);
    cudaGetSymbolAddress((void**)&p_pool, g_pool);
    cudaGetSymbolAddress((void**)&p_sel,  g_sel);
    cudaGetSymbolAddress((void**)&p_xb,   g_xb);
    cudaGetSymbolAddress((void**)&p_qkv_pre, g_qkv_pre);
    cudaGetSymbolAddress((void**)&p_qkv,  g_qkv);
    cudaGetSymbolAddress((void**)&p_ff,   g_ff);
    cudaGetSymbolAddress((void**)&p_xh,   g_xh);
    cudaGetSymbolAddress((void**)&p_det1h, g_det1h);
    cudaGetSymbolAddress((void**)&p_det2h, g_det2h);
    cudaGetSymbolAddress((void**)&p_wbf1, g_wbf1);
    cudaGetSymbolAddress((void**)&p_wbf2, g_wbf2);
    cudaGetSymbolAddress((void**)&p_wbf3, g_wbf3);
    cudaGetSymbolAddress((void**)&p_wt32, g_wt32);

    // dynamic smem caps (host attr calls; not stream ops)
    const int DSM  = 31680 + 46080;            // detector convs
    const int DSB1 = 31680 + 9 * 4 * 2 * 32 * 4 * 4;   // branch layer1 (MS=4): 68544
    const int DSB2 = 31680 + 9 * 2 * 2 * 32 * 4 * 4;   // branch layer2 (MS=2): 50112
    cudaFuncSetAttribute(mmaconvW_k<32,  false>, cudaFuncAttributeMaxDynamicSharedMemorySize, DSM);
    cudaFuncSetAttribute(mmaconvW_k<64,  false>, cudaFuncAttributeMaxDynamicSharedMemorySize, DSM);
    cudaFuncSetAttribute(mmaconvW_k<128, true >, cudaFuncAttributeMaxDynamicSharedMemorySize, DSM);
    cudaFuncSetAttribute(tf32convW_k<32, 64, false>, cudaFuncAttributeMaxDynamicSharedMemorySize, DSB1);
    cudaFuncSetAttribute(tf32convW_k<64, 32, true >, cudaFuncAttributeMaxDynamicSharedMemorySize, DSB2);

    // setup
    cvtz_k<<<(18432 + 73728 + 294912 + 512 + 4 * 18432 + 255) / 256, 256>>>(
        det_w1, det_w2, det_w3, hvi_w1, hvi_w2, ycc_w1, ycc_w2);
    cvt_x_k<<<HWsz / 32, dim3(32, 32)>>>(x);

    // detector (batch 0, bf16 HMMA, all-taps-resident); 4th launch = mmaconvW<64> (ncu target)
    mmaconvW_k<32,  false><<<dim3(6, 96, 1), 256, DSM>>>(p_xh,    p_wbf1, det_b1, p_det1h, nullptr, 64);
    mmaconvW_k<64,  false><<<dim3(6, 96, 2), 256, DSM>>>(p_det1h, p_wbf2, det_b2, p_det2h, nullptr, 128);
    mmaconvW_k<128, true ><<<dim3(6, 96, 4), 256, DSM>>>(p_det2h, p_wbf3, det_b3, nullptr, p_pool, 256);
    logits_k<<<1, 32>>>(det_fcw, det_fcb);

    // branch (TF32 MMA, all-taps-resident, NHWC output; predicated on g_sel)
    tf32convW_k<32, 64, false><<<dim3(6, 96, 4), 256, DSB1>>>(x,     p_wt32 + 0 * 18432, hvi_b1, p_t64, p_sel, 1);
    tf32convW_k<64, 32, true ><<<dim3(6, 96, 4), 256, DSB2>>>(p_t64, p_wt32 + 1 * 18432, hvi_b2, p_xb,  p_sel, 1);
    tf32convW_k<32, 64, false><<<dim3(6, 96, 4), 256, DSB1>>>(x,     p_wt32 + 2 * 18432, ycc_b1, p_t64, p_sel, 2);
    tf32convW_k<64, 32, true ><<<dim3(6, 96, 4), 256, DSB2>>>(p_t64, p_wt32 + 3 * 18432, ycc_b2, p_xb,  p_sel, 2);

    // LN + pw 1x1
    ln_pw_k<<<(NB * HWsz / 2) / 128, 128>>>(x, ln_w, ln_b, pw_w);
    // depthwise 3x3 (96 ch)
    dw4_k<<<(NB * 96 * 36864 + 255) / 256, 256>>>(p_qkv_pre, dw_w, p_qkv, 96, 0, NB * 96 * 36864);
    // fused sumsq + gram
    sg_k<<<512, 256>>>();
    attn_k<<<1, 32>>>(temper);
    // attn apply + proj + residual + ff1 + gelu
    outproj_k<<<dim3(HWsz / 128, 1, NB), 128>>>(x, proj_w, ff1_w);
    // ffdw depthwise + gelu -> out
    dw4_k<<<(NB * 32 * 36864 + 255) / 256, 256>>>(p_ff, ffdw_w, outp, 32, 1, NB * 32 * 36864);

    (void)in_sizes; (void)n_in; (void)out_size;
}